// round 1
// baseline (speedup 1.0000x reference)
#include <cuda_runtime.h>
#include <math.h>

#define BB 4
#define TT 2048
#define CC 1024
#define HH 16
#define HD 64
#define MT (BB*TT)   // 8192

// ---- scratch (static device arrays; no allocation allowed) ----
__device__ float g_q[MT*CC];
__device__ float g_k[MT*CC];
__device__ float g_v[MT*CC];
__device__ float g_y[MT*CC];

// ============================================================
// SGEMM:  Y[m,n] = sum_k X[m,k] * W[n,k] + bias[n]
// X: (MT, CC) row-major, W: (CC, CC) row-major (K contiguous in both)
// Tiles: BM=128, BN=128, BK=16; 256 threads; 8x8 per-thread micro-tile
// ============================================================
__global__ __launch_bounds__(256) void gemm_nt_bias(
    const float* __restrict__ X, const float* __restrict__ W,
    const float* __restrict__ bias, float* __restrict__ Y)
{
    const int BM = 128, BN = 128, BK = 16;
    __shared__ float As[BK][BM + 4];
    __shared__ float Bs[BK][BN + 4];

    const int tid  = threadIdx.x;
    const int m0   = blockIdx.y * BM;
    const int n0   = blockIdx.x * BN;
    const int tRow = tid / 16;        // 0..15
    const int tCol = tid % 16;        // 0..15

    // loader mapping: each thread loads 2 float4 per matrix per K-tile
    const int lr = tid / 4;           // 0..63
    const int lc = (tid % 4) * 4;     // 0,4,8,12

    float acc[8][8];
    #pragma unroll
    for (int i = 0; i < 8; i++)
        #pragma unroll
        for (int j = 0; j < 8; j++) acc[i][j] = 0.f;

    for (int k0 = 0; k0 < CC; k0 += BK) {
        float4 a0 = *(const float4*)(X + (size_t)(m0 + lr     ) * CC + k0 + lc);
        float4 a1 = *(const float4*)(X + (size_t)(m0 + lr + 64) * CC + k0 + lc);
        float4 b0 = *(const float4*)(W + (size_t)(n0 + lr     ) * CC + k0 + lc);
        float4 b1 = *(const float4*)(W + (size_t)(n0 + lr + 64) * CC + k0 + lc);

        As[lc + 0][lr]      = a0.x; As[lc + 1][lr]      = a0.y;
        As[lc + 2][lr]      = a0.z; As[lc + 3][lr]      = a0.w;
        As[lc + 0][lr + 64] = a1.x; As[lc + 1][lr + 64] = a1.y;
        As[lc + 2][lr + 64] = a1.z; As[lc + 3][lr + 64] = a1.w;
        Bs[lc + 0][lr]      = b0.x; Bs[lc + 1][lr]      = b0.y;
        Bs[lc + 2][lr]      = b0.z; Bs[lc + 3][lr]      = b0.w;
        Bs[lc + 0][lr + 64] = b1.x; Bs[lc + 1][lr + 64] = b1.y;
        Bs[lc + 2][lr + 64] = b1.z; Bs[lc + 3][lr + 64] = b1.w;
        __syncthreads();

        #pragma unroll
        for (int kk = 0; kk < BK; kk++) {
            float a[8], b[8];
            *(float4*)(a)     = *(const float4*)&As[kk][tRow * 8];
            *(float4*)(a + 4) = *(const float4*)&As[kk][tRow * 8 + 4];
            *(float4*)(b)     = *(const float4*)&Bs[kk][tCol * 8];
            *(float4*)(b + 4) = *(const float4*)&Bs[kk][tCol * 8 + 4];
            #pragma unroll
            for (int i = 0; i < 8; i++)
                #pragma unroll
                for (int j = 0; j < 8; j++)
                    acc[i][j] = fmaf(a[i], b[j], acc[i][j]);
        }
        __syncthreads();
    }

    float bb[8];
    #pragma unroll
    for (int j = 0; j < 8; j++) bb[j] = bias[n0 + tCol * 8 + j];

    #pragma unroll
    for (int i = 0; i < 8; i++) {
        float* yr = Y + (size_t)(m0 + tRow * 8 + i) * CC + n0 + tCol * 8;
        float4 r0, r1;
        r0.x = acc[i][0] + bb[0]; r0.y = acc[i][1] + bb[1];
        r0.z = acc[i][2] + bb[2]; r0.w = acc[i][3] + bb[3];
        r1.x = acc[i][4] + bb[4]; r1.y = acc[i][5] + bb[5];
        r1.z = acc[i][6] + bb[6]; r1.w = acc[i][7] + bb[7];
        *(float4*)(yr)     = r0;
        *(float4*)(yr + 4) = r1;
    }
}

// ============================================================
// Causal flash attention, fp32.
// Q,K,V,Y all (MT, CC) row-major; head h occupies cols [h*HD, (h+1)*HD).
// Block: 128 threads = 128 queries. KV tile = 32 keys in smem.
// scale = 1/sqrt(C) = 1/32 (reference scales by embedding dim!)
// ============================================================
#define ABM 128
#define ABN 32

__global__ __launch_bounds__(128) void attn_fwd(
    const float* __restrict__ Q, const float* __restrict__ K,
    const float* __restrict__ V, float* __restrict__ Y)
{
    __shared__ float Ks[ABN][HD];
    __shared__ float Vs[ABN][HD];

    const int bh = blockIdx.y;             // 0..B*H-1
    const int b  = bh / HH;
    const int h  = bh % HH;
    const int qt = gridDim.x - 1 - blockIdx.x;   // long blocks first
    const int t0 = qt * ABM;
    const int tid = threadIdx.x;
    const int tq  = t0 + tid;              // this thread's query position

    const float* qrow = Q + (size_t)(b * TT + tq) * CC + h * HD;
    float q[HD];
    #pragma unroll
    for (int d = 0; d < HD; d += 4) {
        float4 v4 = *(const float4*)(qrow + d);
        q[d] = v4.x; q[d + 1] = v4.y; q[d + 2] = v4.z; q[d + 3] = v4.w;
    }

    float acc[HD];
    #pragma unroll
    for (int d = 0; d < HD; d++) acc[d] = 0.f;
    float mi = -1e30f, li = 0.f;
    const float scale = 0.03125f;   // 1/sqrt(1024)

    const int kend = t0 + ABM;      // keys [0, kend) visible to this block
    for (int k0 = 0; k0 < kend; k0 += ABN) {
        // cooperative load of 32x64 K and V tiles (512 float4 each)
        #pragma unroll
        for (int i = 0; i < 4; i++) {
            int e  = tid + i * 128;       // float4 index 0..511
            int r  = e >> 4;              // row 0..31
            int c4 = (e & 15) * 4;
            size_t gbase = (size_t)(b * TT + k0 + r) * CC + h * HD + c4;
            *(float4*)&Ks[r][c4] = *(const float4*)(K + gbase);
            *(float4*)&Vs[r][c4] = *(const float4*)(V + gbase);
        }
        __syncthreads();

        float s[ABN];
        #pragma unroll
        for (int j = 0; j < ABN; j++) {
            float sum = 0.f;
            #pragma unroll
            for (int d = 0; d < HD; d += 4) {
                float4 kv = *(const float4*)&Ks[j][d];
                sum = fmaf(q[d],     kv.x, sum);
                sum = fmaf(q[d + 1], kv.y, sum);
                sum = fmaf(q[d + 2], kv.z, sum);
                sum = fmaf(q[d + 3], kv.w, sum);
            }
            s[j] = sum * scale;
        }

        if (k0 + ABN - 1 > tq) {          // causal mask needed for this thread
            #pragma unroll
            for (int j = 0; j < ABN; j++)
                if (k0 + j > tq) s[j] = -1e30f;
        }

        float mnew = mi;
        #pragma unroll
        for (int j = 0; j < ABN; j++) mnew = fmaxf(mnew, s[j]);
        float corr = __expf(mi - mnew);
        mi = mnew;
        li *= corr;
        #pragma unroll
        for (int d = 0; d < HD; d++) acc[d] *= corr;

        #pragma unroll
        for (int j = 0; j < ABN; j++) {
            float p = __expf(s[j] - mi);
            li += p;
            #pragma unroll
            for (int d = 0; d < HD; d += 4) {
                float4 vv = *(const float4*)&Vs[j][d];
                acc[d]     = fmaf(p, vv.x, acc[d]);
                acc[d + 1] = fmaf(p, vv.y, acc[d + 1]);
                acc[d + 2] = fmaf(p, vv.z, acc[d + 2]);
                acc[d + 3] = fmaf(p, vv.w, acc[d + 3]);
            }
        }
        __syncthreads();
    }

    const float inv = 1.f / li;
    float* yrow = Y + (size_t)(b * TT + tq) * CC + h * HD;
    #pragma unroll
    for (int d = 0; d < HD; d += 4) {
        float4 r;
        r.x = acc[d] * inv; r.y = acc[d + 1] * inv;
        r.z = acc[d + 2] * inv; r.w = acc[d + 3] * inv;
        *(float4*)(yrow + d) = r;
    }
}

// ============================================================
extern "C" void kernel_launch(void* const* d_in, const int* in_sizes, int n_in,
                              void* d_out, int out_size) {
    const float* x  = (const float*)d_in[0];
    const float* Wq = (const float*)d_in[1];
    const float* bq = (const float*)d_in[2];
    const float* Wk = (const float*)d_in[3];
    const float* bk = (const float*)d_in[4];
    const float* Wv = (const float*)d_in[5];
    const float* bv = (const float*)d_in[6];
    const float* Wo = (const float*)d_in[7];
    const float* bo = (const float*)d_in[8];

    float *q, *k, *v, *y;
    cudaGetSymbolAddress((void**)&q, g_q);
    cudaGetSymbolAddress((void**)&k, g_k);
    cudaGetSymbolAddress((void**)&v, g_v);
    cudaGetSymbolAddress((void**)&y, g_y);

    dim3 gemm_grid(CC / 128, MT / 128);
    gemm_nt_bias<<<gemm_grid, 256>>>(x, Wq, bq, q);
    gemm_nt_bias<<<gemm_grid, 256>>>(x, Wk, bk, k);
    gemm_nt_bias<<<gemm_grid, 256>>>(x, Wv, bv, v);

    dim3 attn_grid(TT / ABM, BB * HH);
    attn_fwd<<<attn_grid, 128>>>(q, k, v, y);

    gemm_nt_bias<<<gemm_grid, 256>>>(y, Wo, bo, (float*)d_out);
}

// round 3
// speedup vs baseline: 1.3379x; 1.3379x over previous
#include <cuda_runtime.h>
#include <cuda_bf16.h>
#include <math.h>
#include <stdint.h>

#define BB 4
#define TT 2048
#define CC 1024
#define HH 16
#define HD 64
#define MT (BB*TT)   // 8192

// ---- scratch (static device arrays; no allocation allowed) ----
__device__ float g_q[MT*CC];
__device__ float g_k[MT*CC];
__device__ float g_v[MT*CC];
__device__ float g_y[MT*CC];
__device__ __nv_bfloat16 g_xh[MT*CC];
__device__ __nv_bfloat16 g_xl[MT*CC];
__device__ __nv_bfloat16 g_yh[MT*CC];
__device__ __nv_bfloat16 g_yl[MT*CC];
__device__ __nv_bfloat16 g_wh[4*CC*CC];
__device__ __nv_bfloat16 g_wl[4*CC*CC];

// ============================================================
// PTX helpers (portable: cp.async + ldmatrix + mma.sync, all sm_80+)
// ============================================================
__device__ __forceinline__ uint32_t smem_u32(const void* p) {
    uint32_t a;
    asm("{ .reg .u64 t; cvta.to.shared.u64 t, %1; cvt.u32.u64 %0, t; }" : "=r"(a) : "l"(p));
    return a;
}
#define CP16(dst, src) \
    asm volatile("cp.async.cg.shared.global [%0], [%1], 16;" :: "r"(dst), "l"(src))
#define CP_COMMIT() asm volatile("cp.async.commit_group;" ::: "memory")
#define CP_WAIT1()  asm volatile("cp.async.wait_group 1;" ::: "memory")
#define LDSM4(r0, r1, r2, r3, addr) \
    asm volatile("ldmatrix.sync.aligned.m8n8.x4.shared.b16 {%0,%1,%2,%3}, [%4];" \
                 : "=r"(r0), "=r"(r1), "=r"(r2), "=r"(r3) : "r"(addr))
#define MMA16816(d, a, b0, b1) \
    asm volatile("mma.sync.aligned.m16n8k16.row.col.f32.bf16.bf16.f32 " \
                 "{%0,%1,%2,%3}, {%4,%5,%6,%7}, {%8,%9}, {%0,%1,%2,%3};" \
                 : "+f"((d)[0]), "+f"((d)[1]), "+f"((d)[2]), "+f"((d)[3]) \
                 : "r"((a)[0]), "r"((a)[1]), "r"((a)[2]), "r"((a)[3]), \
                   "r"(b0), "r"(b1))

// ============================================================
// fp32 -> bf16 hi/lo split
// ============================================================
__global__ __launch_bounds__(256) void split_kernel(
    const float4* __restrict__ in, __nv_bfloat162* __restrict__ hi,
    __nv_bfloat162* __restrict__ lo, int n4)
{
    int i = blockIdx.x * blockDim.x + threadIdx.x;
    if (i >= n4) return;
    float4 v = in[i];
    __nv_bfloat16 h0 = __float2bfloat16(v.x), h1 = __float2bfloat16(v.y);
    __nv_bfloat16 h2 = __float2bfloat16(v.z), h3 = __float2bfloat16(v.w);
    __nv_bfloat16 l0 = __float2bfloat16(v.x - __bfloat162float(h0));
    __nv_bfloat16 l1 = __float2bfloat16(v.y - __bfloat162float(h1));
    __nv_bfloat16 l2 = __float2bfloat16(v.z - __bfloat162float(h2));
    __nv_bfloat16 l3 = __float2bfloat16(v.w - __bfloat162float(h3));
    hi[2*i]   = __halves2bfloat162(h0, h1);
    hi[2*i+1] = __halves2bfloat162(h2, h3);
    lo[2*i]   = __halves2bfloat162(l0, l1);
    lo[2*i+1] = __halves2bfloat162(l2, l3);
}

// ============================================================
// HMMA GEMM: Y[m,n] = sum_k A[m,k]*B[n,k] + bias[n]  (fp32 via bf16 split)
// BM=128 BN=128 BK=32, 8 warps (4x2), warp tile 32x64, m16n8k16,
// cp.async double buffer, XOR-swizzled smem.
// ============================================================
#define GBM 128
#define GBN 128
#define GBK 32
#define NKIT (CC/GBK)       // 32
#define TILE_B 8192         // one 128x32 bf16 tile
#define STG_B (4*TILE_B)    // Ah,Al,Bh,Bl per stage = 32768
#define GSMEM (2*STG_B)     // 65536

__device__ __forceinline__ void ld_stage(
    uint32_t sbase, int stage,
    const __nv_bfloat16* __restrict__ Ah, const __nv_bfloat16* __restrict__ Al,
    const __nv_bfloat16* __restrict__ Bh, const __nv_bfloat16* __restrict__ Bl,
    int m0, int n0, int k0, int tid)
{
    uint32_t st = sbase + stage * STG_B;
    #pragma unroll
    for (int t = 0; t < 2; t++) {
        int i = tid + t * 256;          // chunk index 0..511
        int r = i >> 2, c = i & 3;      // row, 16B-chunk in row
        uint32_t soff = ((uint32_t)(r * 4 + (c ^ (r & 3)))) << 4;
        size_t ga = (size_t)(m0 + r) * CC + k0 + c * 8;
        size_t gb = (size_t)(n0 + r) * CC + k0 + c * 8;
        CP16(st + soff,              Ah + ga);
        CP16(st + TILE_B + soff,     Al + ga);
        CP16(st + 2*TILE_B + soff,   Bh + gb);
        CP16(st + 3*TILE_B + soff,   Bl + gb);
    }
}

__global__ __launch_bounds__(256) void gemm_mma(
    const __nv_bfloat16* __restrict__ Ah, const __nv_bfloat16* __restrict__ Al,
    const __nv_bfloat16* __restrict__ Bh, const __nv_bfloat16* __restrict__ Bl,
    const float* __restrict__ bias, float* __restrict__ Y)
{
    extern __shared__ char smem[];
    const uint32_t sbase = smem_u32(smem);
    const int tid = threadIdx.x, wid = tid >> 5, lid = tid & 31;
    const int m0 = blockIdx.y * GBM, n0 = blockIdx.x * GBN;
    const int wm = wid >> 1, wn = wid & 1;   // 4x2 warp grid

    float acc[2][8][4];
    #pragma unroll
    for (int a = 0; a < 2; a++)
        #pragma unroll
        for (int b = 0; b < 8; b++)
            #pragma unroll
            for (int c = 0; c < 4; c++) acc[a][b][c] = 0.f;

    ld_stage(sbase, 0, Ah, Al, Bh, Bl, m0, n0, 0, tid);
    CP_COMMIT();
    ld_stage(sbase, 1, Ah, Al, Bh, Bl, m0, n0, GBK, tid);
    CP_COMMIT();

    // lane-invariant address pieces
    const int a_r  = wm * 32 + (lid & 15);          // + mi*16
    const int a_c  = lid >> 4;                      // + kk*2
    const int b_r  = wn * 64 + (lid & 7) + ((lid >> 4) << 3);   // + nj4*16
    const int b_c  = (lid & 15) >> 3;               // + kk*2

    for (int kb = 0; kb < NKIT; kb++) {
        CP_WAIT1();
        __syncthreads();
        const uint32_t st = sbase + (kb & 1) * STG_B;

        #pragma unroll
        for (int kk = 0; kk < 2; kk++) {
            uint32_t ah[2][4], al[2][4], bh[4][4], bl[4][4];
            #pragma unroll
            for (int mi = 0; mi < 2; mi++) {
                int r = a_r + mi * 16;
                int c16 = kk * 2 + a_c;
                uint32_t off = ((uint32_t)(r * 4 + (c16 ^ (r & 3)))) << 4;
                LDSM4(ah[mi][0], ah[mi][1], ah[mi][2], ah[mi][3], st + off);
                LDSM4(al[mi][0], al[mi][1], al[mi][2], al[mi][3], st + TILE_B + off);
            }
            #pragma unroll
            for (int nj = 0; nj < 4; nj++) {
                int r = b_r + nj * 16;
                int c16 = kk * 2 + b_c;
                uint32_t off = ((uint32_t)(r * 4 + (c16 ^ (r & 3)))) << 4;
                LDSM4(bh[nj][0], bh[nj][1], bh[nj][2], bh[nj][3], st + 2*TILE_B + off);
                LDSM4(bl[nj][0], bl[nj][1], bl[nj][2], bl[nj][3], st + 3*TILE_B + off);
            }
            #pragma unroll
            for (int mi = 0; mi < 2; mi++) {
                #pragma unroll
                for (int nj = 0; nj < 4; nj++) {
                    #pragma unroll
                    for (int half = 0; half < 2; half++) {
                        float* d = acc[mi][nj * 2 + half];
                        uint32_t b0h = bh[nj][half*2], b1h = bh[nj][half*2+1];
                        uint32_t b0l = bl[nj][half*2], b1l = bl[nj][half*2+1];
                        MMA16816(d, ah[mi], b0h, b1h);   // Ah*Bh
                        MMA16816(d, ah[mi], b0l, b1l);   // Ah*Bl
                        MMA16816(d, al[mi], b0h, b1h);   // Al*Bh
                    }
                }
            }
        }
        __syncthreads();
        if (kb + 2 < NKIT)
            ld_stage(sbase, kb & 1, Ah, Al, Bh, Bl, m0, n0, (kb + 2) * GBK, tid);
        CP_COMMIT();
    }

    // epilogue
    #pragma unroll
    for (int mi = 0; mi < 2; mi++) {
        #pragma unroll
        for (int nj = 0; nj < 8; nj++) {
            int row = m0 + wm * 32 + mi * 16 + (lid >> 2);
            int col = n0 + wn * 64 + nj * 8 + (lid & 3) * 2;
            float b0 = __ldg(bias + col), b1 = __ldg(bias + col + 1);
            float2 r0, r1;
            r0.x = acc[mi][nj][0] + b0; r0.y = acc[mi][nj][1] + b1;
            r1.x = acc[mi][nj][2] + b0; r1.y = acc[mi][nj][3] + b1;
            *(float2*)(Y + (size_t)row * CC + col) = r0;
            *(float2*)(Y + (size_t)(row + 8) * CC + col) = r1;
        }
    }
}

// ============================================================
// Causal flash attention, fp32 (unchanged)
// ============================================================
#define ABM 128
#define ABN 32

__global__ __launch_bounds__(128) void attn_fwd(
    const float* __restrict__ Q, const float* __restrict__ K,
    const float* __restrict__ V, float* __restrict__ Y)
{
    __shared__ float Ks[ABN][HD];
    __shared__ float Vs[ABN][HD];

    const int bh = blockIdx.y;
    const int b  = bh / HH;
    const int h  = bh % HH;
    const int qt = gridDim.x - 1 - blockIdx.x;
    const int t0 = qt * ABM;
    const int tid = threadIdx.x;
    const int tq  = t0 + tid;

    const float* qrow = Q + (size_t)(b * TT + tq) * CC + h * HD;
    float q[HD];
    #pragma unroll
    for (int d = 0; d < HD; d += 4) {
        float4 v4 = *(const float4*)(qrow + d);
        q[d] = v4.x; q[d + 1] = v4.y; q[d + 2] = v4.z; q[d + 3] = v4.w;
    }

    float acc[HD];
    #pragma unroll
    for (int d = 0; d < HD; d++) acc[d] = 0.f;
    float mi = -1e30f, li = 0.f;
    const float scale = 0.03125f;

    const int kend = t0 + ABM;
    for (int k0 = 0; k0 < kend; k0 += ABN) {
        #pragma unroll
        for (int i = 0; i < 4; i++) {
            int e  = tid + i * 128;
            int r  = e >> 4;
            int c4 = (e & 15) * 4;
            size_t gbase = (size_t)(b * TT + k0 + r) * CC + h * HD + c4;
            *(float4*)&Ks[r][c4] = *(const float4*)(K + gbase);
            *(float4*)&Vs[r][c4] = *(const float4*)(V + gbase);
        }
        __syncthreads();

        float s[ABN];
        #pragma unroll
        for (int j = 0; j < ABN; j++) {
            float sum = 0.f;
            #pragma unroll
            for (int d = 0; d < HD; d += 4) {
                float4 kv = *(const float4*)&Ks[j][d];
                sum = fmaf(q[d],     kv.x, sum);
                sum = fmaf(q[d + 1], kv.y, sum);
                sum = fmaf(q[d + 2], kv.z, sum);
                sum = fmaf(q[d + 3], kv.w, sum);
            }
            s[j] = sum * scale;
        }

        if (k0 + ABN - 1 > tq) {
            #pragma unroll
            for (int j = 0; j < ABN; j++)
                if (k0 + j > tq) s[j] = -1e30f;
        }

        float mnew = mi;
        #pragma unroll
        for (int j = 0; j < ABN; j++) mnew = fmaxf(mnew, s[j]);
        float corr = __expf(mi - mnew);
        mi = mnew;
        li *= corr;
        #pragma unroll
        for (int d = 0; d < HD; d++) acc[d] *= corr;

        #pragma unroll
        for (int j = 0; j < ABN; j++) {
            float p = __expf(s[j] - mi);
            li += p;
            #pragma unroll
            for (int d = 0; d < HD; d += 4) {
                float4 vv = *(const float4*)&Vs[j][d];
                acc[d]     = fmaf(p, vv.x, acc[d]);
                acc[d + 1] = fmaf(p, vv.y, acc[d + 1]);
                acc[d + 2] = fmaf(p, vv.z, acc[d + 2]);
                acc[d + 3] = fmaf(p, vv.w, acc[d + 3]);
            }
        }
        __syncthreads();
    }

    const float inv = 1.f / li;
    float* yrow = Y + (size_t)(b * TT + tq) * CC + h * HD;
    #pragma unroll
    for (int d = 0; d < HD; d += 4) {
        float4 r;
        r.x = acc[d] * inv; r.y = acc[d + 1] * inv;
        r.z = acc[d + 2] * inv; r.w = acc[d + 3] * inv;
        *(float4*)(yrow + d) = r;
    }
}

// ============================================================
extern "C" void kernel_launch(void* const* d_in, const int* in_sizes, int n_in,
                              void* d_out, int out_size) {
    const float* x  = (const float*)d_in[0];
    const float* Wq = (const float*)d_in[1];
    const float* bq = (const float*)d_in[2];
    const float* Wk = (const float*)d_in[3];
    const float* bk = (const float*)d_in[4];
    const float* Wv = (const float*)d_in[5];
    const float* bv = (const float*)d_in[6];
    const float* Wo = (const float*)d_in[7];
    const float* bo = (const float*)d_in[8];

    float *q, *k, *v, *y;
    __nv_bfloat16 *xh, *xl, *yh, *yl, *wh, *wl;
    cudaGetSymbolAddress((void**)&q,  g_q);
    cudaGetSymbolAddress((void**)&k,  g_k);
    cudaGetSymbolAddress((void**)&v,  g_v);
    cudaGetSymbolAddress((void**)&y,  g_y);
    cudaGetSymbolAddress((void**)&xh, g_xh);
    cudaGetSymbolAddress((void**)&xl, g_xl);
    cudaGetSymbolAddress((void**)&yh, g_yh);
    cudaGetSymbolAddress((void**)&yl, g_yl);
    cudaGetSymbolAddress((void**)&wh, g_wh);
    cudaGetSymbolAddress((void**)&wl, g_wl);

    cudaFuncSetAttribute(gemm_mma, cudaFuncAttributeMaxDynamicSharedMemorySize, GSMEM);

    const int n4x = MT * CC / 4;
    const int n4w = CC * CC / 4;
    split_kernel<<<n4x / 256, 256>>>((const float4*)x, (__nv_bfloat162*)xh, (__nv_bfloat162*)xl, n4x);
    split_kernel<<<n4w / 256, 256>>>((const float4*)Wq, (__nv_bfloat162*)(wh),           (__nv_bfloat162*)(wl),           n4w);
    split_kernel<<<n4w / 256, 256>>>((const float4*)Wk, (__nv_bfloat162*)(wh + CC*CC),   (__nv_bfloat162*)(wl + CC*CC),   n4w);
    split_kernel<<<n4w / 256, 256>>>((const float4*)Wv, (__nv_bfloat162*)(wh + 2*CC*CC), (__nv_bfloat162*)(wl + 2*CC*CC), n4w);
    split_kernel<<<n4w / 256, 256>>>((const float4*)Wo, (__nv_bfloat162*)(wh + 3*CC*CC), (__nv_bfloat162*)(wl + 3*CC*CC), n4w);

    dim3 gg(CC / GBN, MT / GBM);   // (8, 64)
    gemm_mma<<<gg, 256, GSMEM>>>(xh, xl, wh,            wl,            bq, q);
    gemm_mma<<<gg, 256, GSMEM>>>(xh, xl, wh + CC*CC,    wl + CC*CC,    bk, k);
    gemm_mma<<<gg, 256, GSMEM>>>(xh, xl, wh + 2*CC*CC,  wl + 2*CC*CC,  bv, v);

    dim3 ag(TT / ABM, BB * HH);
    attn_fwd<<<ag, 128>>>(q, k, v, y);

    split_kernel<<<n4x / 256, 256>>>((const float4*)y, (__nv_bfloat162*)yh, (__nv_bfloat162*)yl, n4x);
    gemm_mma<<<gg, 256, GSMEM>>>(yh, yl, wh + 3*CC*CC,  wl + 3*CC*CC,  bo, (float*)d_out);
}

// round 5
// speedup vs baseline: 7.6103x; 5.6882x over previous
#include <cuda_runtime.h>
#include <cuda_fp16.h>
#include <math.h>
#include <stdint.h>

#define BB 4
#define TT 2048
#define CC 1024
#define HH 16
#define HD 64
#define MT (BB*TT)   // 8192

// ---- scratch (static device arrays; no allocation allowed) ----
__device__ __half g_x16[MT*CC];
__device__ __half g_w16[4*CC*CC];
__device__ __half g_q16[MT*CC];
__device__ __half g_k16[MT*CC];
__device__ __half g_v16[MT*CC];
__device__ __half g_y16[MT*CC];

// ============================================================
// PTX helpers (portable: cp.async + ldmatrix + mma.sync, sm_80+)
// ============================================================
__device__ __forceinline__ uint32_t smem_u32(const void* p) {
    uint32_t a;
    asm("{ .reg .u64 t; cvta.to.shared.u64 t, %1; cvt.u32.u64 %0, t; }" : "=r"(a) : "l"(p));
    return a;
}
#define CP16(dst, src) \
    asm volatile("cp.async.cg.shared.global [%0], [%1], 16;" :: "r"(dst), "l"(src))
#define CP_COMMIT() asm volatile("cp.async.commit_group;" ::: "memory")
#define CP_WAIT0()  asm volatile("cp.async.wait_group 0;" ::: "memory")
#define CP_WAIT1()  asm volatile("cp.async.wait_group 1;" ::: "memory")
#define LDSM4(r0, r1, r2, r3, addr) \
    asm volatile("ldmatrix.sync.aligned.m8n8.x4.shared.b16 {%0,%1,%2,%3}, [%4];" \
                 : "=r"(r0), "=r"(r1), "=r"(r2), "=r"(r3) : "r"(addr))
#define LDSM4T(r0, r1, r2, r3, addr) \
    asm volatile("ldmatrix.sync.aligned.m8n8.x4.trans.shared.b16 {%0,%1,%2,%3}, [%4];" \
                 : "=r"(r0), "=r"(r1), "=r"(r2), "=r"(r3) : "r"(addr))
#define MMA16816(d, a, b0, b1) \
    asm volatile("mma.sync.aligned.m16n8k16.row.col.f32.f16.f16.f32 " \
                 "{%0,%1,%2,%3}, {%4,%5,%6,%7}, {%8,%9}, {%0,%1,%2,%3};" \
                 : "+f"((d)[0]), "+f"((d)[1]), "+f"((d)[2]), "+f"((d)[3]) \
                 : "r"((a)[0]), "r"((a)[1]), "r"((a)[2]), "r"((a)[3]), \
                   "r"(b0), "r"(b1))

__device__ __forceinline__ uint32_t pack_h2(float a, float b) {
    __half2 h = __floats2half2_rn(a, b);
    return *(uint32_t*)&h;
}

// ============================================================
// fp32 -> fp16 convert
// ============================================================
__global__ __launch_bounds__(256) void to_half(
    const float4* __restrict__ in, __half2* __restrict__ out, int n4)
{
    int i = blockIdx.x * blockDim.x + threadIdx.x;
    if (i >= n4) return;
    float4 v = in[i];
    out[2*i]   = __floats2half2_rn(v.x, v.y);
    out[2*i+1] = __floats2half2_rn(v.z, v.w);
}

// ============================================================
// HMMA GEMM: Y[m,n] = sum_k A[m,k]*B[n,k] + bias[n]   (fp16 in, fp32 accum)
// BM=128 BN=128 BK=32, 8 warps (4x2), warp tile 32x64, m16n8k16,
// cp.async double buffer, XOR-swizzled smem. OutT = __half or float.
// ============================================================
#define GBM 128
#define GBN 128
#define GBK 32
#define NKIT (CC/GBK)       // 32
#define TILE_B 8192         // one 128x32 fp16 tile
#define STG_B (2*TILE_B)    // A,B per stage = 16384
#define GSMEM (2*STG_B)     // 32768

__device__ __forceinline__ void ld_stage(
    uint32_t sbase, int stage,
    const __half* __restrict__ A, const __half* __restrict__ B,
    int m0, int n0, int k0, int tid)
{
    uint32_t st = sbase + stage * STG_B;
    #pragma unroll
    for (int t = 0; t < 2; t++) {
        int i = tid + t * 256;          // chunk index 0..511
        int r = i >> 2, c = i & 3;
        uint32_t soff = ((uint32_t)(r * 4 + (c ^ (r & 3)))) << 4;
        size_t ga = (size_t)(m0 + r) * CC + k0 + c * 8;
        size_t gb = (size_t)(n0 + r) * CC + k0 + c * 8;
        CP16(st + soff,          A + ga);
        CP16(st + TILE_B + soff, B + gb);
    }
}

template <typename OutT>
__global__ __launch_bounds__(256) void gemm_mma(
    const __half* __restrict__ A, const __half* __restrict__ B,
    const float* __restrict__ bias, OutT* __restrict__ Y)
{
    extern __shared__ char smem[];
    const uint32_t sbase = smem_u32(smem);
    const int tid = threadIdx.x, wid = tid >> 5, lid = tid & 31;
    const int m0 = blockIdx.y * GBM, n0 = blockIdx.x * GBN;
    const int wm = wid >> 1, wn = wid & 1;

    float acc[2][8][4];
    #pragma unroll
    for (int a = 0; a < 2; a++)
        #pragma unroll
        for (int b = 0; b < 8; b++)
            #pragma unroll
            for (int c = 0; c < 4; c++) acc[a][b][c] = 0.f;

    ld_stage(sbase, 0, A, B, m0, n0, 0, tid);
    CP_COMMIT();
    ld_stage(sbase, 1, A, B, m0, n0, GBK, tid);
    CP_COMMIT();

    const int a_r = wm * 32 + (lid & 15);
    const int a_c = lid >> 4;
    const int b_r = wn * 64 + (lid & 7) + ((lid >> 4) << 3);
    const int b_c = (lid & 15) >> 3;

    for (int kb = 0; kb < NKIT; kb++) {
        CP_WAIT1();
        __syncthreads();
        const uint32_t st = sbase + (kb & 1) * STG_B;

        #pragma unroll
        for (int kk = 0; kk < 2; kk++) {
            uint32_t af[2][4], bf[4][4];
            #pragma unroll
            for (int mi = 0; mi < 2; mi++) {
                int r = a_r + mi * 16;
                int c16 = kk * 2 + a_c;
                uint32_t off = ((uint32_t)(r * 4 + (c16 ^ (r & 3)))) << 4;
                LDSM4(af[mi][0], af[mi][1], af[mi][2], af[mi][3], st + off);
            }
            #pragma unroll
            for (int nj = 0; nj < 4; nj++) {
                int r = b_r + nj * 16;
                int c16 = kk * 2 + b_c;
                uint32_t off = ((uint32_t)(r * 4 + (c16 ^ (r & 3)))) << 4;
                LDSM4(bf[nj][0], bf[nj][1], bf[nj][2], bf[nj][3], st + TILE_B + off);
            }
            #pragma unroll
            for (int mi = 0; mi < 2; mi++)
                #pragma unroll
                for (int nj = 0; nj < 4; nj++) {
                    MMA16816(acc[mi][nj * 2],     af[mi], bf[nj][0], bf[nj][1]);
                    MMA16816(acc[mi][nj * 2 + 1], af[mi], bf[nj][2], bf[nj][3]);
                }
        }
        __syncthreads();
        if (kb + 2 < NKIT)
            ld_stage(sbase, kb & 1, A, B, m0, n0, (kb + 2) * GBK, tid);
        CP_COMMIT();
    }

    #pragma unroll
    for (int mi = 0; mi < 2; mi++) {
        #pragma unroll
        for (int nj = 0; nj < 8; nj++) {
            int row = m0 + wm * 32 + mi * 16 + (lid >> 2);
            int col = n0 + wn * 64 + nj * 8 + (lid & 3) * 2;
            float b0 = __ldg(bias + col), b1 = __ldg(bias + col + 1);
            float v00 = acc[mi][nj][0] + b0, v01 = acc[mi][nj][1] + b1;
            float v10 = acc[mi][nj][2] + b0, v11 = acc[mi][nj][3] + b1;
            if (sizeof(OutT) == 2) {
                *(__half2*)((__half*)Y + (size_t)row * CC + col)       = __floats2half2_rn(v00, v01);
                *(__half2*)((__half*)Y + (size_t)(row + 8) * CC + col) = __floats2half2_rn(v10, v11);
            } else {
                *(float2*)((float*)Y + (size_t)row * CC + col)       = make_float2(v00, v01);
                *(float2*)((float*)Y + (size_t)(row + 8) * CC + col) = make_float2(v10, v11);
            }
        }
    }
}

// ============================================================
// Flash attention (causal) with m16n8k16 fp16 HMMA.
// BM=64 queries (4 warps x 16 rows), BN=64 keys, HD=64.
// Q,K,V,Y: fp16 (MT, CC) row-major, head h at cols [h*64, h*64+64).
// scale = 1/sqrt(C) = 1/32.
// ============================================================
#define AQ 64
#define AK 64

__global__ __launch_bounds__(128) void attn_mma(
    const __half* __restrict__ Q, const __half* __restrict__ K,
    const __half* __restrict__ V, __half* __restrict__ Y)
{
    __shared__ __align__(1024) char sm[40960];
    // layout: sQ[0,8K) sK0[8K,16K) sK1[16K,24K) sV0[24K,32K) sV1[32K,40K)
    const uint32_t sb = smem_u32(sm);

    const int tid = threadIdx.x, wid = tid >> 5, lid = tid & 31;
    const int bh = blockIdx.y;
    const int b  = bh / HH;
    const int h  = bh % HH;
    const int qb = gridDim.x - 1 - blockIdx.x;
    const int t0 = qb * AQ;
    const int nkv = qb + 1;

    const size_t headoff = (size_t)b * TT * CC + (size_t)h * HD;
    const __half* Qg = Q + headoff + (size_t)t0 * CC;

    // ---- load Q tile (64x64) to smem ----
    #pragma unroll
    for (int i = 0; i < 4; i++) {
        int idx = tid + i * 128;          // 0..511
        int r = idx >> 3, ch = idx & 7;
        uint32_t soff = (uint32_t)(r * 128 + ((ch ^ (r & 7)) << 4));
        CP16(sb + soff, Qg + (size_t)r * CC + ch * 8);
    }
    CP_COMMIT();

    // ---- KV tile loader ----
    auto ld_kv = [&](int buf, int kb) {
        const __half* Kg = K + headoff + (size_t)(kb * AK) * CC;
        const __half* Vg = V + headoff + (size_t)(kb * AK) * CC;
        uint32_t kb32 = sb + 8192 + buf * 8192;
        uint32_t vb32 = sb + 24576 + buf * 8192;
        #pragma unroll
        for (int i = 0; i < 4; i++) {
            int idx = tid + i * 128;
            int r = idx >> 3, ch = idx & 7;
            uint32_t soff = (uint32_t)(r * 128 + ((ch ^ (r & 7)) << 4));
            CP16(kb32 + soff, Kg + (size_t)r * CC + ch * 8);
            CP16(vb32 + soff, Vg + (size_t)r * CC + ch * 8);
        }
        CP_COMMIT();
    };

    ld_kv(0, 0);
    if (nkv > 1) ld_kv(1, 1);

    uint32_t qf[4][4];
    float acc[8][4];
    #pragma unroll
    for (int n = 0; n < 8; n++)
        #pragma unroll
        for (int c = 0; c < 4; c++) acc[n][c] = 0.f;
    float m0 = -1e30f, m1 = -1e30f, l0 = 0.f, l1 = 0.f;
    const float scale = 0.03125f;

    const int g = lid >> 2;               // row in group
    const int tg = lid & 3;               // col pair
    const int r0loc = wid * 16 + g;       // local query row (row0)

    for (int kb = 0; kb < nkv; kb++) {
        if (kb + 1 < nkv) { CP_WAIT1(); } else { CP_WAIT0(); }
        __syncthreads();

        if (kb == 0) {
            // load Q fragments once
            #pragma unroll
            for (int kk = 0; kk < 4; kk++) {
                int row = wid * 16 + (lid & 7) + ((lid >> 3) & 1) * 8;
                int ch  = 2 * kk + (lid >> 4);
                uint32_t addr = sb + (uint32_t)(row * 128 + ((ch ^ (row & 7)) << 4));
                LDSM4(qf[kk][0], qf[kk][1], qf[kk][2], qf[kk][3], addr);
            }
        }

        const uint32_t kbase = sb + 8192 + (kb & 1) * 8192;
        const uint32_t vbase = sb + 24576 + (kb & 1) * 8192;

        // ---- S = Q K^T ----
        float s[8][4];
        #pragma unroll
        for (int j = 0; j < 8; j++)
            #pragma unroll
            for (int c = 0; c < 4; c++) s[j][c] = 0.f;

        #pragma unroll
        for (int kk = 0; kk < 4; kk++) {
            #pragma unroll
            for (int jp = 0; jp < 4; jp++) {
                int t = lid >> 3;
                int j = 2 * jp + (t >> 1);
                int ch = 2 * kk + (t & 1);
                int keyrow = 8 * j + (lid & 7);
                uint32_t addr = kbase + (uint32_t)(keyrow * 128 + ((ch ^ (keyrow & 7)) << 4));
                uint32_t f0, f1, f2, f3;
                LDSM4(f0, f1, f2, f3, addr);
                MMA16816(s[2 * jp],     qf[kk], f0, f1);
                MMA16816(s[2 * jp + 1], qf[kk], f2, f3);
            }
        }

        // scale + causal mask (only last tile needs mask)
        #pragma unroll
        for (int j = 0; j < 8; j++)
            #pragma unroll
            for (int c = 0; c < 4; c++) s[j][c] *= scale;

        if (kb == qb) {
            #pragma unroll
            for (int j = 0; j < 8; j++) {
                int kc = 8 * j + tg * 2;
                if (kc     > r0loc)     s[j][0] = -1e30f;
                if (kc + 1 > r0loc)     s[j][1] = -1e30f;
                if (kc     > r0loc + 8) s[j][2] = -1e30f;
                if (kc + 1 > r0loc + 8) s[j][3] = -1e30f;
            }
        }

        // ---- online softmax ----
        float tm0 = -1e30f, tm1 = -1e30f;
        #pragma unroll
        for (int j = 0; j < 8; j++) {
            tm0 = fmaxf(tm0, fmaxf(s[j][0], s[j][1]));
            tm1 = fmaxf(tm1, fmaxf(s[j][2], s[j][3]));
        }
        tm0 = fmaxf(tm0, __shfl_xor_sync(0xffffffffu, tm0, 1));
        tm0 = fmaxf(tm0, __shfl_xor_sync(0xffffffffu, tm0, 2));
        tm1 = fmaxf(tm1, __shfl_xor_sync(0xffffffffu, tm1, 1));
        tm1 = fmaxf(tm1, __shfl_xor_sync(0xffffffffu, tm1, 2));

        float mn0 = fmaxf(m0, tm0), mn1 = fmaxf(m1, tm1);
        float cr0 = __expf(m0 - mn0), cr1 = __expf(m1 - mn1);
        m0 = mn0; m1 = mn1;

        float rs0 = 0.f, rs1 = 0.f;
        #pragma unroll
        for (int j = 0; j < 8; j++) {
            s[j][0] = __expf(s[j][0] - mn0);
            s[j][1] = __expf(s[j][1] - mn0);
            s[j][2] = __expf(s[j][2] - mn1);
            s[j][3] = __expf(s[j][3] - mn1);
            rs0 += s[j][0] + s[j][1];
            rs1 += s[j][2] + s[j][3];
        }
        rs0 += __shfl_xor_sync(0xffffffffu, rs0, 1);
        rs0 += __shfl_xor_sync(0xffffffffu, rs0, 2);
        rs1 += __shfl_xor_sync(0xffffffffu, rs1, 1);
        rs1 += __shfl_xor_sync(0xffffffffu, rs1, 2);
        l0 = l0 * cr0 + rs0;
        l1 = l1 * cr1 + rs1;

        #pragma unroll
        for (int n = 0; n < 8; n++) {
            acc[n][0] *= cr0; acc[n][1] *= cr0;
            acc[n][2] *= cr1; acc[n][3] *= cr1;
        }

        // pack P fragments
        uint32_t ap[4][4];
        #pragma unroll
        for (int kk = 0; kk < 4; kk++) {
            ap[kk][0] = pack_h2(s[2*kk][0],   s[2*kk][1]);
            ap[kk][1] = pack_h2(s[2*kk][2],   s[2*kk][3]);
            ap[kk][2] = pack_h2(s[2*kk+1][0], s[2*kk+1][1]);
            ap[kk][3] = pack_h2(s[2*kk+1][2], s[2*kk+1][3]);
        }

        // ---- acc += P V ----
        #pragma unroll
        for (int kk = 0; kk < 4; kk++) {
            #pragma unroll
            for (int np = 0; np < 4; np++) {
                int t = lid >> 3;
                int n = 2 * np + (t >> 1);
                int keyrow = 16 * kk + (t & 1) * 8 + (lid & 7);
                uint32_t addr = vbase + (uint32_t)(keyrow * 128 + ((n ^ (keyrow & 7)) << 4));
                uint32_t f0, f1, f2, f3;
                LDSM4T(f0, f1, f2, f3, addr);
                MMA16816(acc[2 * np],     ap[kk], f0, f1);
                MMA16816(acc[2 * np + 1], ap[kk], f2, f3);
            }
        }

        __syncthreads();
        if (kb + 2 < nkv) ld_kv(kb & 1, kb + 2);
    }

    // ---- epilogue ----
    float inv0 = 1.f / l0, inv1 = 1.f / l1;
    __half* Y0 = Y + headoff + (size_t)(t0 + wid * 16 + g) * CC + tg * 2;
    __half* Y1 = Y0 + 8 * CC;
    #pragma unroll
    for (int n = 0; n < 8; n++) {
        *(__half2*)(Y0 + n * 8) = __floats2half2_rn(acc[n][0] * inv0, acc[n][1] * inv0);
        *(__half2*)(Y1 + n * 8) = __floats2half2_rn(acc[n][2] * inv1, acc[n][3] * inv1);
    }
}

// ============================================================
extern "C" void kernel_launch(void* const* d_in, const int* in_sizes, int n_in,
                              void* d_out, int out_size) {
    const float* x  = (const float*)d_in[0];
    const float* Wq = (const float*)d_in[1];
    const float* bq = (const float*)d_in[2];
    const float* Wk = (const float*)d_in[3];
    const float* bk = (const float*)d_in[4];
    const float* Wv = (const float*)d_in[5];
    const float* bv = (const float*)d_in[6];
    const float* Wo = (const float*)d_in[7];
    const float* bo = (const float*)d_in[8];

    __half *x16, *w16, *q16, *k16, *v16, *y16;
    cudaGetSymbolAddress((void**)&x16, g_x16);
    cudaGetSymbolAddress((void**)&w16, g_w16);
    cudaGetSymbolAddress((void**)&q16, g_q16);
    cudaGetSymbolAddress((void**)&k16, g_k16);
    cudaGetSymbolAddress((void**)&v16, g_v16);
    cudaGetSymbolAddress((void**)&y16, g_y16);

    cudaFuncSetAttribute(gemm_mma<__half>, cudaFuncAttributeMaxDynamicSharedMemorySize, GSMEM);
    cudaFuncSetAttribute(gemm_mma<float>,  cudaFuncAttributeMaxDynamicSharedMemorySize, GSMEM);

    const int n4x = MT * CC / 4;
    const int n4w = CC * CC / 4;
    to_half<<<n4x / 256, 256>>>((const float4*)x,  (__half2*)x16, n4x);
    to_half<<<n4w / 256, 256>>>((const float4*)Wq, (__half2*)(w16),            n4w);
    to_half<<<n4w / 256, 256>>>((const float4*)Wk, (__half2*)(w16 + CC*CC),    n4w);
    to_half<<<n4w / 256, 256>>>((const float4*)Wv, (__half2*)(w16 + 2*CC*CC),  n4w);
    to_half<<<n4w / 256, 256>>>((const float4*)Wo, (__half2*)(w16 + 3*CC*CC),  n4w);

    dim3 gg(CC / GBN, MT / GBM);   // (8, 64)
    gemm_mma<__half><<<gg, 256, GSMEM>>>(x16, w16,            bq, q16);
    gemm_mma<__half><<<gg, 256, GSMEM>>>(x16, w16 + CC*CC,    bk, k16);
    gemm_mma<__half><<<gg, 256, GSMEM>>>(x16, w16 + 2*CC*CC,  bv, v16);

    dim3 ag(TT / AQ, BB * HH);     // (32, 64)
    attn_mma<<<ag, 128>>>(q16, k16, v16, y16);

    gemm_mma<float><<<gg, 256, GSMEM>>>(y16, w16 + 3*CC*CC, bo, (float*)d_out);
}

// round 6
// speedup vs baseline: 7.9780x; 1.0483x over previous
#include <cuda_runtime.h>
#include <cuda_fp16.h>
#include <math.h>
#include <stdint.h>

#define BB 4
#define TT 2048
#define CC 1024
#define HH 16
#define HD 64
#define MT (BB*TT)   // 8192
#define QS (3*CC)    // fused QKV row stride = 3072

// ---- scratch (static device arrays; no allocation allowed) ----
__device__ __half g_x16[MT*CC];
__device__ __half g_w16[4*CC*CC];     // Wq,Wk,Wv packed + Wo
__device__ float  g_bqkv[QS];
__device__ __half g_qkv16[(size_t)MT*QS];
__device__ __half g_y16[MT*CC];

// ============================================================
// PTX helpers
// ============================================================
__device__ __forceinline__ uint32_t smem_u32(const void* p) {
    uint32_t a;
    asm("{ .reg .u64 t; cvta.to.shared.u64 t, %1; cvt.u32.u64 %0, t; }" : "=r"(a) : "l"(p));
    return a;
}
#define CP16(dst, src) \
    asm volatile("cp.async.cg.shared.global [%0], [%1], 16;" :: "r"(dst), "l"(src))
#define CP_COMMIT() asm volatile("cp.async.commit_group;" ::: "memory")
#define CP_WAIT0()  asm volatile("cp.async.wait_group 0;" ::: "memory")
#define CP_WAIT1()  asm volatile("cp.async.wait_group 1;" ::: "memory")
#define CP_WAIT2()  asm volatile("cp.async.wait_group 2;" ::: "memory")
#define LDSM4(r0, r1, r2, r3, addr) \
    asm volatile("ldmatrix.sync.aligned.m8n8.x4.shared.b16 {%0,%1,%2,%3}, [%4];" \
                 : "=r"(r0), "=r"(r1), "=r"(r2), "=r"(r3) : "r"(addr))
#define LDSM4T(r0, r1, r2, r3, addr) \
    asm volatile("ldmatrix.sync.aligned.m8n8.x4.trans.shared.b16 {%0,%1,%2,%3}, [%4];" \
                 : "=r"(r0), "=r"(r1), "=r"(r2), "=r"(r3) : "r"(addr))
#define MMA16816(d, a, b0, b1) \
    asm volatile("mma.sync.aligned.m16n8k16.row.col.f32.f16.f16.f32 " \
                 "{%0,%1,%2,%3}, {%4,%5,%6,%7}, {%8,%9}, {%0,%1,%2,%3};" \
                 : "+f"((d)[0]), "+f"((d)[1]), "+f"((d)[2]), "+f"((d)[3]) \
                 : "r"((a)[0]), "r"((a)[1]), "r"((a)[2]), "r"((a)[3]), \
                   "r"(b0), "r"(b1))

__device__ __forceinline__ uint32_t pack_h2(float a, float b) {
    __half2 h = __floats2half2_rn(a, b);
    return *(uint32_t*)&h;
}

// ============================================================
// fp32 -> fp16 convert (grid-stride, ILP)
// ============================================================
__global__ __launch_bounds__(256) void to_half(
    const float4* __restrict__ in, __half2* __restrict__ out, int n4)
{
    int stride = gridDim.x * blockDim.x;
    for (int i = blockIdx.x * blockDim.x + threadIdx.x; i < n4; i += stride) {
        float4 v = in[i];
        out[2*i]   = __floats2half2_rn(v.x, v.y);
        out[2*i+1] = __floats2half2_rn(v.z, v.w);
    }
}

__global__ void pack_bias(const float* __restrict__ bq, const float* __restrict__ bk,
                          const float* __restrict__ bv, float* __restrict__ o)
{
    int i = blockIdx.x * blockDim.x + threadIdx.x;   // 0..3071
    const float* src = (i < CC) ? bq : (i < 2*CC) ? bk : bv;
    o[i] = src[i & (CC - 1)];
}

// ============================================================
// HMMA GEMM: Y[m,n] = sum_k A[m,k]*B[n,k] + bias[n]
// BM=128 BN=256 BK=32, 8 warps (2x4), warp tile 64x64, m16n8k16,
// 3-stage cp.async, XOR-swizzled smem. OutT = __half or float. ldc param.
// ============================================================
#define GBM 128
#define GBN 256
#define GBK 32
#define NKIT (CC/GBK)        // 32
#define A_B 8192             // 128x32 fp16
#define B_B 16384            // 256x32 fp16
#define STG_B (A_B + B_B)    // 24576
#define NSTG 3
#define GSMEM (NSTG*STG_B)   // 73728

__device__ __forceinline__ void ld_stage(
    uint32_t sbase, int stage,
    const __half* __restrict__ A, const __half* __restrict__ B,
    int m0, int n0, int k0, int tid)
{
    uint32_t st = sbase + stage * STG_B;
    #pragma unroll
    for (int t = 0; t < 2; t++) {        // A: 512 chunks
        int i = tid + t * 256;
        int r = i >> 2, c = i & 3;
        uint32_t soff = ((uint32_t)(r * 4 + (c ^ (r & 3)))) << 4;
        CP16(st + soff, A + (size_t)(m0 + r) * CC + k0 + c * 8);
    }
    #pragma unroll
    for (int t = 0; t < 4; t++) {        // B: 1024 chunks
        int i = tid + t * 256;
        int r = i >> 2, c = i & 3;
        uint32_t soff = ((uint32_t)(r * 4 + (c ^ (r & 3)))) << 4;
        CP16(st + A_B + soff, B + (size_t)(n0 + r) * CC + k0 + c * 8);
    }
}

template <typename OutT>
__global__ __launch_bounds__(256, 1) void gemm_mma(
    const __half* __restrict__ A, const __half* __restrict__ B,
    const float* __restrict__ bias, OutT* __restrict__ Y, int ldc)
{
    extern __shared__ char smem[];
    const uint32_t sbase = smem_u32(smem);
    const int tid = threadIdx.x, wid = tid >> 5, lid = tid & 31;
    const int m0 = blockIdx.y * GBM, n0 = blockIdx.x * GBN;
    const int wm = wid >> 2, wn = wid & 3;     // 2x4 warp grid, tile 64x64

    float acc[4][8][4];
    #pragma unroll
    for (int a = 0; a < 4; a++)
        #pragma unroll
        for (int b = 0; b < 8; b++)
            #pragma unroll
            for (int c = 0; c < 4; c++) acc[a][b][c] = 0.f;

    ld_stage(sbase, 0, A, B, m0, n0, 0, tid);       CP_COMMIT();
    ld_stage(sbase, 1, A, B, m0, n0, GBK, tid);     CP_COMMIT();
    ld_stage(sbase, 2, A, B, m0, n0, 2 * GBK, tid); CP_COMMIT();

    const int a_r = wm * 64 + (lid & 15);
    const int a_c = lid >> 4;
    const int b_r = wn * 64 + (lid & 7) + ((lid >> 4) << 3);
    const int b_c = (lid & 15) >> 3;

    int stage = 0;
    for (int kb = 0; kb < NKIT; kb++) {
        CP_WAIT2();
        __syncthreads();
        const uint32_t st = sbase + stage * STG_B;

        #pragma unroll
        for (int kk = 0; kk < 2; kk++) {
            uint32_t af[4][4], bf[4][4];
            #pragma unroll
            for (int mi = 0; mi < 4; mi++) {
                int r = a_r + mi * 16;
                int c16 = kk * 2 + a_c;
                uint32_t off = ((uint32_t)(r * 4 + (c16 ^ (r & 3)))) << 4;
                LDSM4(af[mi][0], af[mi][1], af[mi][2], af[mi][3], st + off);
            }
            #pragma unroll
            for (int nj = 0; nj < 4; nj++) {
                int r = b_r + nj * 16;
                int c16 = kk * 2 + b_c;
                uint32_t off = ((uint32_t)(r * 4 + (c16 ^ (r & 3)))) << 4;
                LDSM4(bf[nj][0], bf[nj][1], bf[nj][2], bf[nj][3], st + A_B + off);
            }
            #pragma unroll
            for (int mi = 0; mi < 4; mi++)
                #pragma unroll
                for (int nj = 0; nj < 4; nj++) {
                    MMA16816(acc[mi][nj * 2],     af[mi], bf[nj][0], bf[nj][1]);
                    MMA16816(acc[mi][nj * 2 + 1], af[mi], bf[nj][2], bf[nj][3]);
                }
        }
        __syncthreads();
        if (kb + NSTG < NKIT) {
            ld_stage(sbase, stage, A, B, m0, n0, (kb + NSTG) * GBK, tid);
        }
        CP_COMMIT();
        stage = (stage + 1 == NSTG) ? 0 : stage + 1;
    }

    #pragma unroll
    for (int mi = 0; mi < 4; mi++) {
        #pragma unroll
        for (int nj = 0; nj < 8; nj++) {
            int row = m0 + wm * 64 + mi * 16 + (lid >> 2);
            int col = n0 + wn * 64 + nj * 8 + (lid & 3) * 2;
            float b0 = __ldg(bias + col), b1 = __ldg(bias + col + 1);
            float v00 = acc[mi][nj][0] + b0, v01 = acc[mi][nj][1] + b1;
            float v10 = acc[mi][nj][2] + b0, v11 = acc[mi][nj][3] + b1;
            if (sizeof(OutT) == 2) {
                *(__half2*)((__half*)Y + (size_t)row * ldc + col)       = __floats2half2_rn(v00, v01);
                *(__half2*)((__half*)Y + (size_t)(row + 8) * ldc + col) = __floats2half2_rn(v10, v11);
            } else {
                *(float2*)((float*)Y + (size_t)row * ldc + col)       = make_float2(v00, v01);
                *(float2*)((float*)Y + (size_t)(row + 8) * ldc + col) = make_float2(v10, v11);
            }
        }
    }
}

// ============================================================
// Flash attention (causal), m16n8k16 fp16 HMMA.
// QKV fused buffer (MT, 3072): Q cols [0,1024), K [1024,2048), V [2048,3072);
// head h at +h*64. Y: fp16 (MT, CC). scale = 1/32.
// ============================================================
#define AQ 64
#define AK 64

__global__ __launch_bounds__(128) void attn_mma(
    const __half* __restrict__ QKV, __half* __restrict__ Y)
{
    __shared__ __align__(1024) char sm[40960];
    const uint32_t sb = smem_u32(sm);

    const int tid = threadIdx.x, wid = tid >> 5, lid = tid & 31;
    const int bh = blockIdx.y;
    const int b  = bh / HH;
    const int h  = bh % HH;
    const int qb = gridDim.x - 1 - blockIdx.x;
    const int t0 = qb * AQ;
    const int nkv = qb + 1;

    const size_t headoff = (size_t)b * TT * QS + (size_t)h * HD;
    const __half* Qg = QKV + headoff + (size_t)t0 * QS;

    #pragma unroll
    for (int i = 0; i < 4; i++) {
        int idx = tid + i * 128;
        int r = idx >> 3, ch = idx & 7;
        uint32_t soff = (uint32_t)(r * 128 + ((ch ^ (r & 7)) << 4));
        CP16(sb + soff, Qg + (size_t)r * QS + ch * 8);
    }
    CP_COMMIT();

    auto ld_kv = [&](int buf, int kb) {
        const __half* Kg = QKV + CC   + headoff + (size_t)(kb * AK) * QS;
        const __half* Vg = QKV + 2*CC + headoff + (size_t)(kb * AK) * QS;
        uint32_t kb32 = sb + 8192 + buf * 8192;
        uint32_t vb32 = sb + 24576 + buf * 8192;
        #pragma unroll
        for (int i = 0; i < 4; i++) {
            int idx = tid + i * 128;
            int r = idx >> 3, ch = idx & 7;
            uint32_t soff = (uint32_t)(r * 128 + ((ch ^ (r & 7)) << 4));
            CP16(kb32 + soff, Kg + (size_t)r * QS + ch * 8);
            CP16(vb32 + soff, Vg + (size_t)r * QS + ch * 8);
        }
        CP_COMMIT();
    };

    ld_kv(0, 0);
    if (nkv > 1) ld_kv(1, 1);

    uint32_t qf[4][4];
    float acc[8][4];
    #pragma unroll
    for (int n = 0; n < 8; n++)
        #pragma unroll
        for (int c = 0; c < 4; c++) acc[n][c] = 0.f;
    float m0 = -1e30f, m1 = -1e30f, l0 = 0.f, l1 = 0.f;
    const float scale = 0.03125f;

    const int g = lid >> 2;
    const int tg = lid & 3;
    const int r0loc = wid * 16 + g;

    for (int kb = 0; kb < nkv; kb++) {
        if (kb + 1 < nkv) { CP_WAIT1(); } else { CP_WAIT0(); }
        __syncthreads();

        if (kb == 0) {
            #pragma unroll
            for (int kk = 0; kk < 4; kk++) {
                int row = wid * 16 + (lid & 7) + ((lid >> 3) & 1) * 8;
                int ch  = 2 * kk + (lid >> 4);
                uint32_t addr = sb + (uint32_t)(row * 128 + ((ch ^ (row & 7)) << 4));
                LDSM4(qf[kk][0], qf[kk][1], qf[kk][2], qf[kk][3], addr);
            }
        }

        const uint32_t kbase = sb + 8192 + (kb & 1) * 8192;
        const uint32_t vbase = sb + 24576 + (kb & 1) * 8192;

        float s[8][4];
        #pragma unroll
        for (int j = 0; j < 8; j++)
            #pragma unroll
            for (int c = 0; c < 4; c++) s[j][c] = 0.f;

        #pragma unroll
        for (int kk = 0; kk < 4; kk++) {
            #pragma unroll
            for (int jp = 0; jp < 4; jp++) {
                int t = lid >> 3;
                int j = 2 * jp + (t >> 1);
                int ch = 2 * kk + (t & 1);
                int keyrow = 8 * j + (lid & 7);
                uint32_t addr = kbase + (uint32_t)(keyrow * 128 + ((ch ^ (keyrow & 7)) << 4));
                uint32_t f0, f1, f2, f3;
                LDSM4(f0, f1, f2, f3, addr);
                MMA16816(s[2 * jp],     qf[kk], f0, f1);
                MMA16816(s[2 * jp + 1], qf[kk], f2, f3);
            }
        }

        #pragma unroll
        for (int j = 0; j < 8; j++)
            #pragma unroll
            for (int c = 0; c < 4; c++) s[j][c] *= scale;

        if (kb == qb) {
            #pragma unroll
            for (int j = 0; j < 8; j++) {
                int kc = 8 * j + tg * 2;
                if (kc     > r0loc)     s[j][0] = -1e30f;
                if (kc + 1 > r0loc)     s[j][1] = -1e30f;
                if (kc     > r0loc + 8) s[j][2] = -1e30f;
                if (kc + 1 > r0loc + 8) s[j][3] = -1e30f;
            }
        }

        float tm0 = -1e30f, tm1 = -1e30f;
        #pragma unroll
        for (int j = 0; j < 8; j++) {
            tm0 = fmaxf(tm0, fmaxf(s[j][0], s[j][1]));
            tm1 = fmaxf(tm1, fmaxf(s[j][2], s[j][3]));
        }
        tm0 = fmaxf(tm0, __shfl_xor_sync(0xffffffffu, tm0, 1));
        tm0 = fmaxf(tm0, __shfl_xor_sync(0xffffffffu, tm0, 2));
        tm1 = fmaxf(tm1, __shfl_xor_sync(0xffffffffu, tm1, 1));
        tm1 = fmaxf(tm1, __shfl_xor_sync(0xffffffffu, tm1, 2));

        float mn0 = fmaxf(m0, tm0), mn1 = fmaxf(m1, tm1);
        float cr0 = __expf(m0 - mn0), cr1 = __expf(m1 - mn1);
        m0 = mn0; m1 = mn1;

        float rs0 = 0.f, rs1 = 0.f;
        #pragma unroll
        for (int j = 0; j < 8; j++) {
            s[j][0] = __expf(s[j][0] - mn0);
            s[j][1] = __expf(s[j][1] - mn0);
            s[j][2] = __expf(s[j][2] - mn1);
            s[j][3] = __expf(s[j][3] - mn1);
            rs0 += s[j][0] + s[j][1];
            rs1 += s[j][2] + s[j][3];
        }
        rs0 += __shfl_xor_sync(0xffffffffu, rs0, 1);
        rs0 += __shfl_xor_sync(0xffffffffu, rs0, 2);
        rs1 += __shfl_xor_sync(0xffffffffu, rs1, 1);
        rs1 += __shfl_xor_sync(0xffffffffu, rs1, 2);
        l0 = l0 * cr0 + rs0;
        l1 = l1 * cr1 + rs1;

        #pragma unroll
        for (int n = 0; n < 8; n++) {
            acc[n][0] *= cr0; acc[n][1] *= cr0;
            acc[n][2] *= cr1; acc[n][3] *= cr1;
        }

        uint32_t ap[4][4];
        #pragma unroll
        for (int kk = 0; kk < 4; kk++) {
            ap[kk][0] = pack_h2(s[2*kk][0],   s[2*kk][1]);
            ap[kk][1] = pack_h2(s[2*kk][2],   s[2*kk][3]);
            ap[kk][2] = pack_h2(s[2*kk+1][0], s[2*kk+1][1]);
            ap[kk][3] = pack_h2(s[2*kk+1][2], s[2*kk+1][3]);
        }

        #pragma unroll
        for (int kk = 0; kk < 4; kk++) {
            #pragma unroll
            for (int np = 0; np < 4; np++) {
                int t = lid >> 3;
                int n = 2 * np + (t >> 1);
                int keyrow = 16 * kk + (t & 1) * 8 + (lid & 7);
                uint32_t addr = vbase + (uint32_t)(keyrow * 128 + ((n ^ (keyrow & 7)) << 4));
                uint32_t f0, f1, f2, f3;
                LDSM4T(f0, f1, f2, f3, addr);
                MMA16816(acc[2 * np],     ap[kk], f0, f1);
                MMA16816(acc[2 * np + 1], ap[kk], f2, f3);
            }
        }

        __syncthreads();
        if (kb + 2 < nkv) ld_kv(kb & 1, kb + 2);
    }

    float inv0 = 1.f / l0, inv1 = 1.f / l1;
    const size_t yoff = (size_t)b * TT * CC + (size_t)h * HD;
    __half* Y0 = Y + yoff + (size_t)(t0 + wid * 16 + g) * CC + tg * 2;
    __half* Y1 = Y0 + 8 * CC;
    #pragma unroll
    for (int n = 0; n < 8; n++) {
        *(__half2*)(Y0 + n * 8) = __floats2half2_rn(acc[n][0] * inv0, acc[n][1] * inv0);
        *(__half2*)(Y1 + n * 8) = __floats2half2_rn(acc[n][2] * inv1, acc[n][3] * inv1);
    }
}

// ============================================================
extern "C" void kernel_launch(void* const* d_in, const int* in_sizes, int n_in,
                              void* d_out, int out_size) {
    const float* x  = (const float*)d_in[0];
    const float* Wq = (const float*)d_in[1];
    const float* bq = (const float*)d_in[2];
    const float* Wk = (const float*)d_in[3];
    const float* bk = (const float*)d_in[4];
    const float* Wv = (const float*)d_in[5];
    const float* bv = (const float*)d_in[6];
    const float* Wo = (const float*)d_in[7];
    const float* bo = (const float*)d_in[8];

    __half *x16, *w16, *qkv16, *y16;
    float *bqkv;
    cudaGetSymbolAddress((void**)&x16,   g_x16);
    cudaGetSymbolAddress((void**)&w16,   g_w16);
    cudaGetSymbolAddress((void**)&qkv16, g_qkv16);
    cudaGetSymbolAddress((void**)&y16,   g_y16);
    cudaGetSymbolAddress((void**)&bqkv,  g_bqkv);

    cudaFuncSetAttribute(gemm_mma<__half>, cudaFuncAttributeMaxDynamicSharedMemorySize, GSMEM);
    cudaFuncSetAttribute(gemm_mma<float>,  cudaFuncAttributeMaxDynamicSharedMemorySize, GSMEM);

    const int n4x = MT * CC / 4;
    const int n4w = CC * CC / 4;
    to_half<<<1024, 256>>>((const float4*)x,  (__half2*)x16, n4x);
    to_half<<<512, 256>>>((const float4*)Wq, (__half2*)(w16),            n4w);
    to_half<<<512, 256>>>((const float4*)Wk, (__half2*)(w16 + CC*CC),    n4w);
    to_half<<<512, 256>>>((const float4*)Wv, (__half2*)(w16 + 2*CC*CC),  n4w);
    to_half<<<512, 256>>>((const float4*)Wo, (__half2*)(w16 + 3*CC*CC),  n4w);
    pack_bias<<<QS / 256, 256>>>(bq, bk, bv, bqkv);

    dim3 gqkv(QS / GBN, MT / GBM);   // (12, 64)
    gemm_mma<__half><<<gqkv, 256, GSMEM>>>(x16, w16, bqkv, qkv16, QS);

    dim3 ag(TT / AQ, BB * HH);       // (32, 64)
    attn_mma<<<ag, 128>>>(qkv16, y16);

    dim3 go(CC / GBN, MT / GBM);     // (4, 64)
    gemm_mma<float><<<go, 256, GSMEM>>>(y16, w16 + 3*CC*CC, bo, (float*)d_out, CC);
}

// round 7
// speedup vs baseline: 8.8612x; 1.1107x over previous
#include <cuda_runtime.h>
#include <cuda_fp16.h>
#include <math.h>
#include <stdint.h>

#define BB 4
#define TT 2048
#define CC 1024
#define HH 16
#define HD 64
#define MT (BB*TT)   // 8192
#define QS (3*CC)    // fused QKV row stride = 3072

// ---- scratch (static device arrays; no allocation allowed) ----
__device__ __half g_x16[MT*CC];
__device__ __half g_w16[4*CC*CC];     // Wq,Wk,Wv packed + Wo
__device__ float  g_bqkv[QS];
__device__ __half g_qkv16[(size_t)MT*QS];
__device__ __half g_y16[MT*CC];

// ============================================================
// PTX helpers
// ============================================================
__device__ __forceinline__ uint32_t smem_u32(const void* p) {
    uint32_t a;
    asm("{ .reg .u64 t; cvta.to.shared.u64 t, %1; cvt.u32.u64 %0, t; }" : "=r"(a) : "l"(p));
    return a;
}
#define CP16(dst, src) \
    asm volatile("cp.async.cg.shared.global [%0], [%1], 16;" :: "r"(dst), "l"(src))
#define CP_COMMIT() asm volatile("cp.async.commit_group;" ::: "memory")
#define CP_WAIT0()  asm volatile("cp.async.wait_group 0;" ::: "memory")
#define CP_WAIT1()  asm volatile("cp.async.wait_group 1;" ::: "memory")
#define CP_WAIT2()  asm volatile("cp.async.wait_group 2;" ::: "memory")
#define LDSM4(r0, r1, r2, r3, addr) \
    asm volatile("ldmatrix.sync.aligned.m8n8.x4.shared.b16 {%0,%1,%2,%3}, [%4];" \
                 : "=r"(r0), "=r"(r1), "=r"(r2), "=r"(r3) : "r"(addr))
#define LDSM4T(r0, r1, r2, r3, addr) \
    asm volatile("ldmatrix.sync.aligned.m8n8.x4.trans.shared.b16 {%0,%1,%2,%3}, [%4];" \
                 : "=r"(r0), "=r"(r1), "=r"(r2), "=r"(r3) : "r"(addr))
#define MMA16816(d, a, b0, b1) \
    asm volatile("mma.sync.aligned.m16n8k16.row.col.f32.f16.f16.f32 " \
                 "{%0,%1,%2,%3}, {%4,%5,%6,%7}, {%8,%9}, {%0,%1,%2,%3};" \
                 : "+f"((d)[0]), "+f"((d)[1]), "+f"((d)[2]), "+f"((d)[3]) \
                 : "r"((a)[0]), "r"((a)[1]), "r"((a)[2]), "r"((a)[3]), \
                   "r"(b0), "r"(b1))

__device__ __forceinline__ uint32_t pack_h2(float a, float b) {
    __half2 h = __floats2half2_rn(a, b);
    return *(uint32_t*)&h;
}

// ============================================================
// Fused fp32 -> fp16 convert: x (MT*CC) + 4 weights (CC*CC each)
// ============================================================
#define N4X (MT*CC/4)       // 2097152
#define N4W (CC*CC/4)       // 262144
#define N4TOT (N4X + 4*N4W) // 3145728

__global__ __launch_bounds__(256) void cvt_all(
    const float4* __restrict__ x,
    const float4* __restrict__ w0, const float4* __restrict__ w1,
    const float4* __restrict__ w2, const float4* __restrict__ w3,
    __half2* __restrict__ xd, __half2* __restrict__ wd)
{
    const int stride = gridDim.x * blockDim.x;
    for (int i = blockIdx.x * blockDim.x + threadIdx.x; i < N4TOT; i += stride) {
        const float4* s; __half2* d; int off;
        if (i < N4X) { s = x; d = xd; off = i; }
        else {
            int j = i - N4X;
            int rg = j >> 18;                 // N4W = 2^18
            off = j & (N4W - 1);
            s = (rg == 0) ? w0 : (rg == 1) ? w1 : (rg == 2) ? w2 : w3;
            d = wd + (size_t)rg * (2 * N4W);
        }
        float4 v = s[off];
        d[2*off]   = __floats2half2_rn(v.x, v.y);
        d[2*off+1] = __floats2half2_rn(v.z, v.w);
    }
}

__global__ void pack_bias(const float* __restrict__ bq, const float* __restrict__ bk,
                          const float* __restrict__ bv, float* __restrict__ o)
{
    int i = blockIdx.x * blockDim.x + threadIdx.x;   // 0..3071
    const float* src = (i < CC) ? bq : (i < 2*CC) ? bk : bv;
    o[i] = src[i & (CC - 1)];
}

// ============================================================
// HMMA GEMM: Y[m,n] = sum_k A[m,k]*B[n,k] + bias[n]
// BM=128 BN=128 BK=32, 4 warps (2x2), warp tile 64x64, m16n8k16,
// 3-stage cp.async, XOR-swizzled smem, 2 CTAs/SM.
// ============================================================
#define GBM 128
#define GBN 128
#define GBK 32
#define NKIT (CC/GBK)        // 32
#define A_B 8192             // 128x32 fp16
#define B_B 8192
#define STG_B (A_B + B_B)    // 16384
#define NSTG 3
#define GSMEM (NSTG*STG_B)   // 49152

__device__ __forceinline__ void ld_stage(
    uint32_t sbase, int stage,
    const __half* __restrict__ A, const __half* __restrict__ B,
    int m0, int n0, int k0, int tid)
{
    uint32_t st = sbase + stage * STG_B;
    #pragma unroll
    for (int t = 0; t < 4; t++) {        // 512 chunks each for A and B
        int i = tid + t * 128;
        int r = i >> 2, c = i & 3;
        uint32_t soff = ((uint32_t)(r * 4 + (c ^ (r & 3)))) << 4;
        CP16(st + soff,       A + (size_t)(m0 + r) * CC + k0 + c * 8);
        CP16(st + A_B + soff, B + (size_t)(n0 + r) * CC + k0 + c * 8);
    }
}

template <typename OutT>
__global__ __launch_bounds__(128, 2) void gemm_mma(
    const __half* __restrict__ A, const __half* __restrict__ B,
    const float* __restrict__ bias, OutT* __restrict__ Y, int ldc)
{
    extern __shared__ char smem[];
    const uint32_t sbase = smem_u32(smem);
    const int tid = threadIdx.x, wid = tid >> 5, lid = tid & 31;
    const int m0 = blockIdx.y * GBM, n0 = blockIdx.x * GBN;
    const int wm = wid >> 1, wn = wid & 1;     // 2x2 warp grid, tile 64x64

    float acc[4][8][4];
    #pragma unroll
    for (int a = 0; a < 4; a++)
        #pragma unroll
        for (int b = 0; b < 8; b++)
            #pragma unroll
            for (int c = 0; c < 4; c++) acc[a][b][c] = 0.f;

    ld_stage(sbase, 0, A, B, m0, n0, 0, tid);       CP_COMMIT();
    ld_stage(sbase, 1, A, B, m0, n0, GBK, tid);     CP_COMMIT();
    ld_stage(sbase, 2, A, B, m0, n0, 2 * GBK, tid); CP_COMMIT();

    const int a_r = wm * 64 + (lid & 15);
    const int a_c = lid >> 4;
    const int b_r = wn * 64 + (lid & 7) + ((lid >> 4) << 3);
    const int b_c = (lid & 15) >> 3;

    int stage = 0;
    for (int kb = 0; kb < NKIT; kb++) {
        CP_WAIT2();
        __syncthreads();
        const uint32_t st = sbase + stage * STG_B;

        #pragma unroll
        for (int kk = 0; kk < 2; kk++) {
            uint32_t af[4][4], bf[4][4];
            #pragma unroll
            for (int mi = 0; mi < 4; mi++) {
                int r = a_r + mi * 16;
                int c16 = kk * 2 + a_c;
                uint32_t off = ((uint32_t)(r * 4 + (c16 ^ (r & 3)))) << 4;
                LDSM4(af[mi][0], af[mi][1], af[mi][2], af[mi][3], st + off);
            }
            #pragma unroll
            for (int nj = 0; nj < 4; nj++) {
                int r = b_r + nj * 16;
                int c16 = kk * 2 + b_c;
                uint32_t off = ((uint32_t)(r * 4 + (c16 ^ (r & 3)))) << 4;
                LDSM4(bf[nj][0], bf[nj][1], bf[nj][2], bf[nj][3], st + A_B + off);
            }
            #pragma unroll
            for (int mi = 0; mi < 4; mi++)
                #pragma unroll
                for (int nj = 0; nj < 4; nj++) {
                    MMA16816(acc[mi][nj * 2],     af[mi], bf[nj][0], bf[nj][1]);
                    MMA16816(acc[mi][nj * 2 + 1], af[mi], bf[nj][2], bf[nj][3]);
                }
        }
        __syncthreads();
        if (kb + NSTG < NKIT) {
            ld_stage(sbase, stage, A, B, m0, n0, (kb + NSTG) * GBK, tid);
        }
        CP_COMMIT();
        stage = (stage + 1 == NSTG) ? 0 : stage + 1;
    }

    #pragma unroll
    for (int mi = 0; mi < 4; mi++) {
        #pragma unroll
        for (int nj = 0; nj < 8; nj++) {
            int row = m0 + wm * 64 + mi * 16 + (lid >> 2);
            int col = n0 + wn * 64 + nj * 8 + (lid & 3) * 2;
            float b0 = __ldg(bias + col), b1 = __ldg(bias + col + 1);
            float v00 = acc[mi][nj][0] + b0, v01 = acc[mi][nj][1] + b1;
            float v10 = acc[mi][nj][2] + b0, v11 = acc[mi][nj][3] + b1;
            if (sizeof(OutT) == 2) {
                *(__half2*)((__half*)Y + (size_t)row * ldc + col)       = __floats2half2_rn(v00, v01);
                *(__half2*)((__half*)Y + (size_t)(row + 8) * ldc + col) = __floats2half2_rn(v10, v11);
            } else {
                *(float2*)((float*)Y + (size_t)row * ldc + col)       = make_float2(v00, v01);
                *(float2*)((float*)Y + (size_t)(row + 8) * ldc + col) = make_float2(v10, v11);
            }
        }
    }
}

// ============================================================
// Flash attention (causal), m16n8k16 fp16 HMMA.
// AQ=128 queries/CTA (8 warps x 16 rows), AK=64 keys/tile.
// QKV fused buffer (MT, 3072): Q [0,1024), K [1024,2048), V [2048,3072);
// head h at +h*64. Y: fp16 (MT, CC). scale = 1/32.
// ============================================================
#define AQ 128
#define AK 64

__global__ __launch_bounds__(256) void attn_mma(
    const __half* __restrict__ QKV, __half* __restrict__ Y)
{
    // Q [0,16K) | K0 [16K,24K) K1 [24K,32K) | V0 [32K,40K) V1 [40K,48K)
    __shared__ __align__(1024) char sm[49152];
    const uint32_t sb = smem_u32(sm);

    const int tid = threadIdx.x, wid = tid >> 5, lid = tid & 31;
    const int bh = blockIdx.y;
    const int b  = bh / HH;
    const int h  = bh % HH;
    const int qt = gridDim.x - 1 - blockIdx.x;   // long blocks first
    const int t0 = qt * AQ;
    const int nkv = 2 * qt + 2;                  // key tiles of 64

    const size_t headoff = (size_t)b * TT * QS + (size_t)h * HD;
    const __half* Qg = QKV + headoff + (size_t)t0 * QS;

    // ---- load Q tile (128x64) ----
    #pragma unroll
    for (int i = 0; i < 4; i++) {
        int idx = tid + i * 256;          // 0..1023
        int r = idx >> 3, ch = idx & 7;
        uint32_t soff = (uint32_t)(r * 128 + ((ch ^ (r & 7)) << 4));
        CP16(sb + soff, Qg + (size_t)r * QS + ch * 8);
    }
    CP_COMMIT();

    auto ld_kv = [&](int buf, int kb) {
        const __half* Kg = QKV + CC   + headoff + (size_t)(kb * AK) * QS;
        const __half* Vg = QKV + 2*CC + headoff + (size_t)(kb * AK) * QS;
        uint32_t kb32 = sb + 16384 + buf * 8192;
        uint32_t vb32 = sb + 32768 + buf * 8192;
        #pragma unroll
        for (int i = 0; i < 2; i++) {
            int idx = tid + i * 256;      // 0..511
            int r = idx >> 3, ch = idx & 7;
            uint32_t soff = (uint32_t)(r * 128 + ((ch ^ (r & 7)) << 4));
            CP16(kb32 + soff, Kg + (size_t)r * QS + ch * 8);
            CP16(vb32 + soff, Vg + (size_t)r * QS + ch * 8);
        }
        CP_COMMIT();
    };

    ld_kv(0, 0);
    ld_kv(1, 1);

    uint32_t qf[4][4];
    float acc[8][4];
    #pragma unroll
    for (int n = 0; n < 8; n++)
        #pragma unroll
        for (int c = 0; c < 4; c++) acc[n][c] = 0.f;
    float m0 = -1e30f, m1 = -1e30f, l0 = 0.f, l1 = 0.f;
    const float scale = 0.03125f;

    const int g = lid >> 2;
    const int tg = lid & 3;
    const int qg0 = t0 + wid * 16 + g;    // global query row (row0)

    for (int kb = 0; kb < nkv; kb++) {
        if (kb + 1 < nkv) { CP_WAIT1(); } else { CP_WAIT0(); }
        __syncthreads();

        if (kb == 0) {
            #pragma unroll
            for (int kk = 0; kk < 4; kk++) {
                int row = wid * 16 + (lid & 7) + ((lid >> 3) & 1) * 8;
                int ch  = 2 * kk + (lid >> 4);
                uint32_t addr = sb + (uint32_t)(row * 128 + ((ch ^ (row & 7)) << 4));
                LDSM4(qf[kk][0], qf[kk][1], qf[kk][2], qf[kk][3], addr);
            }
        }

        const uint32_t kbase = sb + 16384 + (kb & 1) * 8192;
        const uint32_t vbase = sb + 32768 + (kb & 1) * 8192;

        float s[8][4];
        #pragma unroll
        for (int j = 0; j < 8; j++)
            #pragma unroll
            for (int c = 0; c < 4; c++) s[j][c] = 0.f;

        #pragma unroll
        for (int kk = 0; kk < 4; kk++) {
            #pragma unroll
            for (int jp = 0; jp < 4; jp++) {
                int t = lid >> 3;
                int j = 2 * jp + (t >> 1);
                int ch = 2 * kk + (t & 1);
                int keyrow = 8 * j + (lid & 7);
                uint32_t addr = kbase + (uint32_t)(keyrow * 128 + ((ch ^ (keyrow & 7)) << 4));
                uint32_t f0, f1, f2, f3;
                LDSM4(f0, f1, f2, f3, addr);
                MMA16816(s[2 * jp],     qf[kk], f0, f1);
                MMA16816(s[2 * jp + 1], qf[kk], f2, f3);
            }
        }

        #pragma unroll
        for (int j = 0; j < 8; j++)
            #pragma unroll
            for (int c = 0; c < 4; c++) s[j][c] *= scale;

        if (kb >= nkv - 2) {     // only last two key tiles can hit the diagonal
            #pragma unroll
            for (int j = 0; j < 8; j++) {
                int kc = kb * AK + 8 * j + tg * 2;
                if (kc     > qg0)     s[j][0] = -1e30f;
                if (kc + 1 > qg0)     s[j][1] = -1e30f;
                if (kc     > qg0 + 8) s[j][2] = -1e30f;
                if (kc + 1 > qg0 + 8) s[j][3] = -1e30f;
            }
        }

        float tm0 = -1e30f, tm1 = -1e30f;
        #pragma unroll
        for (int j = 0; j < 8; j++) {
            tm0 = fmaxf(tm0, fmaxf(s[j][0], s[j][1]));
            tm1 = fmaxf(tm1, fmaxf(s[j][2], s[j][3]));
        }
        tm0 = fmaxf(tm0, __shfl_xor_sync(0xffffffffu, tm0, 1));
        tm0 = fmaxf(tm0, __shfl_xor_sync(0xffffffffu, tm0, 2));
        tm1 = fmaxf(tm1, __shfl_xor_sync(0xffffffffu, tm1, 1));
        tm1 = fmaxf(tm1, __shfl_xor_sync(0xffffffffu, tm1, 2));

        float mn0 = fmaxf(m0, tm0), mn1 = fmaxf(m1, tm1);
        float cr0 = __expf(m0 - mn0), cr1 = __expf(m1 - mn1);
        m0 = mn0; m1 = mn1;

        float rs0 = 0.f, rs1 = 0.f;
        #pragma unroll
        for (int j = 0; j < 8; j++) {
            s[j][0] = __expf(s[j][0] - mn0);
            s[j][1] = __expf(s[j][1] - mn0);
            s[j][2] = __expf(s[j][2] - mn1);
            s[j][3] = __expf(s[j][3] - mn1);
            rs0 += s[j][0] + s[j][1];
            rs1 += s[j][2] + s[j][3];
        }
        rs0 += __shfl_xor_sync(0xffffffffu, rs0, 1);
        rs0 += __shfl_xor_sync(0xffffffffu, rs0, 2);
        rs1 += __shfl_xor_sync(0xffffffffu, rs1, 1);
        rs1 += __shfl_xor_sync(0xffffffffu, rs1, 2);
        l0 = l0 * cr0 + rs0;
        l1 = l1 * cr1 + rs1;

        #pragma unroll
        for (int n = 0; n < 8; n++) {
            acc[n][0] *= cr0; acc[n][1] *= cr0;
            acc[n][2] *= cr1; acc[n][3] *= cr1;
        }

        uint32_t ap[4][4];
        #pragma unroll
        for (int kk = 0; kk < 4; kk++) {
            ap[kk][0] = pack_h2(s[2*kk][0],   s[2*kk][1]);
            ap[kk][1] = pack_h2(s[2*kk][2],   s[2*kk][3]);
            ap[kk][2] = pack_h2(s[2*kk+1][0], s[2*kk+1][1]);
            ap[kk][3] = pack_h2(s[2*kk+1][2], s[2*kk+1][3]);
        }

        #pragma unroll
        for (int kk = 0; kk < 4; kk++) {
            #pragma unroll
            for (int np = 0; np < 4; np++) {
                int t = lid >> 3;
                int n = 2 * np + (t >> 1);
                int keyrow = 16 * kk + (t & 1) * 8 + (lid & 7);
                uint32_t addr = vbase + (uint32_t)(keyrow * 128 + ((n ^ (keyrow & 7)) << 4));
                uint32_t f0, f1, f2, f3;
                LDSM4T(f0, f1, f2, f3, addr);
                MMA16816(acc[2 * np],     ap[kk], f0, f1);
                MMA16816(acc[2 * np + 1], ap[kk], f2, f3);
            }
        }

        __syncthreads();
        if (kb + 2 < nkv) ld_kv(kb & 1, kb + 2);
    }

    float inv0 = 1.f / l0, inv1 = 1.f / l1;
    const size_t yoff = (size_t)b * TT * CC + (size_t)h * HD;
    __half* Y0 = Y + yoff + (size_t)(t0 + wid * 16 + g) * CC + tg * 2;
    __half* Y1 = Y0 + 8 * CC;
    #pragma unroll
    for (int n = 0; n < 8; n++) {
        *(__half2*)(Y0 + n * 8) = __floats2half2_rn(acc[n][0] * inv0, acc[n][1] * inv0);
        *(__half2*)(Y1 + n * 8) = __floats2half2_rn(acc[n][2] * inv1, acc[n][3] * inv1);
    }
}

// ============================================================
extern "C" void kernel_launch(void* const* d_in, const int* in_sizes, int n_in,
                              void* d_out, int out_size) {
    const float* x  = (const float*)d_in[0];
    const float* Wq = (const float*)d_in[1];
    const float* bq = (const float*)d_in[2];
    const float* Wk = (const float*)d_in[3];
    const float* bk = (const float*)d_in[4];
    const float* Wv = (const float*)d_in[5];
    const float* bv = (const float*)d_in[6];
    const float* Wo = (const float*)d_in[7];
    const float* bo = (const float*)d_in[8];

    __half *x16, *w16, *qkv16, *y16;
    float *bqkv;
    cudaGetSymbolAddress((void**)&x16,   g_x16);
    cudaGetSymbolAddress((void**)&w16,   g_w16);
    cudaGetSymbolAddress((void**)&qkv16, g_qkv16);
    cudaGetSymbolAddress((void**)&y16,   g_y16);
    cudaGetSymbolAddress((void**)&bqkv,  g_bqkv);

    cudaFuncSetAttribute(gemm_mma<__half>, cudaFuncAttributeMaxDynamicSharedMemorySize, GSMEM);
    cudaFuncSetAttribute(gemm_mma<float>,  cudaFuncAttributeMaxDynamicSharedMemorySize, GSMEM);

    cvt_all<<<3072, 256>>>((const float4*)x, (const float4*)Wq, (const float4*)Wk,
                           (const float4*)Wv, (const float4*)Wo,
                           (__half2*)x16, (__half2*)w16);
    pack_bias<<<QS / 256, 256>>>(bq, bk, bv, bqkv);

    dim3 gqkv(QS / GBN, MT / GBM);   // (24, 64)
    gemm_mma<__half><<<gqkv, 128, GSMEM>>>(x16, w16, bqkv, qkv16, QS);

    dim3 ag(TT / AQ, BB * HH);       // (16, 64)
    attn_mma<<<ag, 256>>>(qkv16, y16);

    dim3 go(CC / GBN, MT / GBM);     // (8, 64)
    gemm_mma<float><<<go, 128, GSMEM>>>(y16, w16 + 3*CC*CC, bo, (float*)d_out, CC);
}

// round 8
// speedup vs baseline: 9.3063x; 1.0502x over previous
#include <cuda_runtime.h>
#include <cuda_fp16.h>
#include <math.h>
#include <stdint.h>

#define BB 4
#define TT 2048
#define CC 1024
#define HH 16
#define HD 64
#define MT (BB*TT)   // 8192
#define QS (3*CC)    // fused QKV row stride = 3072

// ---- scratch (static device arrays; no allocation allowed) ----
__device__ __half g_x16[MT*CC];
__device__ __half g_w16[4*CC*CC];     // Wq,Wk,Wv packed + Wo
__device__ float  g_bqkv[QS];
__device__ __half g_qkv16[(size_t)MT*QS];
__device__ __half g_y16[MT*CC];

// ============================================================
// PTX helpers
// ============================================================
__device__ __forceinline__ uint32_t smem_u32(const void* p) {
    uint32_t a;
    asm("{ .reg .u64 t; cvta.to.shared.u64 t, %1; cvt.u32.u64 %0, t; }" : "=r"(a) : "l"(p));
    return a;
}
#define CP16(dst, src) \
    asm volatile("cp.async.cg.shared.global [%0], [%1], 16;" :: "r"(dst), "l"(src))
#define CP_COMMIT() asm volatile("cp.async.commit_group;" ::: "memory")
#define CP_WAIT0()  asm volatile("cp.async.wait_group 0;" ::: "memory")
#define CP_WAIT1()  asm volatile("cp.async.wait_group 1;" ::: "memory")
#define CP_WAIT2()  asm volatile("cp.async.wait_group 2;" ::: "memory")
#define LDSM4(r0, r1, r2, r3, addr) \
    asm volatile("ldmatrix.sync.aligned.m8n8.x4.shared.b16 {%0,%1,%2,%3}, [%4];" \
                 : "=r"(r0), "=r"(r1), "=r"(r2), "=r"(r3) : "r"(addr))
#define LDSM4T(r0, r1, r2, r3, addr) \
    asm volatile("ldmatrix.sync.aligned.m8n8.x4.trans.shared.b16 {%0,%1,%2,%3}, [%4];" \
                 : "=r"(r0), "=r"(r1), "=r"(r2), "=r"(r3) : "r"(addr))
#define MMA16816(d, a, b0, b1) \
    asm volatile("mma.sync.aligned.m16n8k16.row.col.f32.f16.f16.f32 " \
                 "{%0,%1,%2,%3}, {%4,%5,%6,%7}, {%8,%9}, {%0,%1,%2,%3};" \
                 : "+f"((d)[0]), "+f"((d)[1]), "+f"((d)[2]), "+f"((d)[3]) \
                 : "r"((a)[0]), "r"((a)[1]), "r"((a)[2]), "r"((a)[3]), \
                   "r"(b0), "r"(b1))

// exp2 of two fp32 args -> packed fp16x2 (lo, hi)
__device__ __forceinline__ uint32_t exp2_pair(float lo, float hi) {
    uint32_t h, d;
    asm("cvt.rn.f16x2.f32 %0, %1, %2;" : "=r"(h) : "f"(hi), "f"(lo));
    asm("ex2.approx.f16x2 %0, %1;" : "=r"(d) : "r"(h));
    return d;
}

// ============================================================
// Fused fp32 -> fp16 convert: x (MT*CC) + 4 weights (CC*CC each)
// ============================================================
#define N4X (MT*CC/4)       // 2097152
#define N4W (CC*CC/4)       // 262144
#define N4TOT (N4X + 4*N4W) // 3145728

__global__ __launch_bounds__(256) void cvt_all(
    const float4* __restrict__ x,
    const float4* __restrict__ w0, const float4* __restrict__ w1,
    const float4* __restrict__ w2, const float4* __restrict__ w3,
    __half2* __restrict__ xd, __half2* __restrict__ wd)
{
    const int stride = gridDim.x * blockDim.x;
    for (int i = blockIdx.x * blockDim.x + threadIdx.x; i < N4TOT; i += stride) {
        const float4* s; __half2* d; int off;
        if (i < N4X) { s = x; d = xd; off = i; }
        else {
            int j = i - N4X;
            int rg = j >> 18;                 // N4W = 2^18
            off = j & (N4W - 1);
            s = (rg == 0) ? w0 : (rg == 1) ? w1 : (rg == 2) ? w2 : w3;
            d = wd + (size_t)rg * (2 * N4W);
        }
        float4 v = s[off];
        d[2*off]   = __floats2half2_rn(v.x, v.y);
        d[2*off+1] = __floats2half2_rn(v.z, v.w);
    }
}

__global__ void pack_bias(const float* __restrict__ bq, const float* __restrict__ bk,
                          const float* __restrict__ bv, float* __restrict__ o)
{
    int i = blockIdx.x * blockDim.x + threadIdx.x;   // 0..3071
    const float* src = (i < CC) ? bq : (i < 2*CC) ? bk : bv;
    o[i] = src[i & (CC - 1)];
}

// ============================================================
// HMMA GEMM: Y[m,n] = sum_k A[m,k]*B[n,k] + bias[n]
// BM=128 BN=128 BK=32, 4 warps (2x2), warp tile 64x64, m16n8k16,
// 3-stage cp.async, XOR-swizzled smem, 2 CTAs/SM.
// ============================================================
#define GBM 128
#define GBN 128
#define GBK 32
#define NKIT (CC/GBK)        // 32
#define A_B 8192             // 128x32 fp16
#define B_B 8192
#define STG_B (A_B + B_B)    // 16384
#define NSTG 3
#define GSMEM (NSTG*STG_B)   // 49152

__device__ __forceinline__ void ld_stage(
    uint32_t sbase, int stage,
    const __half* __restrict__ A, const __half* __restrict__ B,
    int m0, int n0, int k0, int tid)
{
    uint32_t st = sbase + stage * STG_B;
    #pragma unroll
    for (int t = 0; t < 4; t++) {        // 512 chunks each for A and B
        int i = tid + t * 128;
        int r = i >> 2, c = i & 3;
        uint32_t soff = ((uint32_t)(r * 4 + (c ^ (r & 3)))) << 4;
        CP16(st + soff,       A + (size_t)(m0 + r) * CC + k0 + c * 8);
        CP16(st + A_B + soff, B + (size_t)(n0 + r) * CC + k0 + c * 8);
    }
}

template <typename OutT>
__global__ __launch_bounds__(128, 2) void gemm_mma(
    const __half* __restrict__ A, const __half* __restrict__ B,
    const float* __restrict__ bias, OutT* __restrict__ Y, int ldc)
{
    extern __shared__ char smem[];
    const uint32_t sbase = smem_u32(smem);
    const int tid = threadIdx.x, wid = tid >> 5, lid = tid & 31;
    const int m0 = blockIdx.y * GBM, n0 = blockIdx.x * GBN;
    const int wm = wid >> 1, wn = wid & 1;     // 2x2 warp grid, tile 64x64

    float acc[4][8][4];
    #pragma unroll
    for (int a = 0; a < 4; a++)
        #pragma unroll
        for (int b = 0; b < 8; b++)
            #pragma unroll
            for (int c = 0; c < 4; c++) acc[a][b][c] = 0.f;

    ld_stage(sbase, 0, A, B, m0, n0, 0, tid);       CP_COMMIT();
    ld_stage(sbase, 1, A, B, m0, n0, GBK, tid);     CP_COMMIT();
    ld_stage(sbase, 2, A, B, m0, n0, 2 * GBK, tid); CP_COMMIT();

    const int a_r = wm * 64 + (lid & 15);
    const int a_c = lid >> 4;
    const int b_r = wn * 64 + (lid & 7) + ((lid >> 4) << 3);
    const int b_c = (lid & 15) >> 3;

    int stage = 0;
    for (int kb = 0; kb < NKIT; kb++) {
        CP_WAIT2();
        __syncthreads();
        const uint32_t st = sbase + stage * STG_B;

        #pragma unroll
        for (int kk = 0; kk < 2; kk++) {
            uint32_t af[4][4], bf[4][4];
            #pragma unroll
            for (int mi = 0; mi < 4; mi++) {
                int r = a_r + mi * 16;
                int c16 = kk * 2 + a_c;
                uint32_t off = ((uint32_t)(r * 4 + (c16 ^ (r & 3)))) << 4;
                LDSM4(af[mi][0], af[mi][1], af[mi][2], af[mi][3], st + off);
            }
            #pragma unroll
            for (int nj = 0; nj < 4; nj++) {
                int r = b_r + nj * 16;
                int c16 = kk * 2 + b_c;
                uint32_t off = ((uint32_t)(r * 4 + (c16 ^ (r & 3)))) << 4;
                LDSM4(bf[nj][0], bf[nj][1], bf[nj][2], bf[nj][3], st + A_B + off);
            }
            #pragma unroll
            for (int mi = 0; mi < 4; mi++)
                #pragma unroll
                for (int nj = 0; nj < 4; nj++) {
                    MMA16816(acc[mi][nj * 2],     af[mi], bf[nj][0], bf[nj][1]);
                    MMA16816(acc[mi][nj * 2 + 1], af[mi], bf[nj][2], bf[nj][3]);
                }
        }
        __syncthreads();
        if (kb + NSTG < NKIT) {
            ld_stage(sbase, stage, A, B, m0, n0, (kb + NSTG) * GBK, tid);
        }
        CP_COMMIT();
        stage = (stage + 1 == NSTG) ? 0 : stage + 1;
    }

    #pragma unroll
    for (int mi = 0; mi < 4; mi++) {
        #pragma unroll
        for (int nj = 0; nj < 8; nj++) {
            int row = m0 + wm * 64 + mi * 16 + (lid >> 2);
            int col = n0 + wn * 64 + nj * 8 + (lid & 3) * 2;
            float b0 = __ldg(bias + col), b1 = __ldg(bias + col + 1);
            float v00 = acc[mi][nj][0] + b0, v01 = acc[mi][nj][1] + b1;
            float v10 = acc[mi][nj][2] + b0, v11 = acc[mi][nj][3] + b1;
            if (sizeof(OutT) == 2) {
                *(__half2*)((__half*)Y + (size_t)row * ldc + col)       = __floats2half2_rn(v00, v01);
                *(__half2*)((__half*)Y + (size_t)(row + 8) * ldc + col) = __floats2half2_rn(v10, v11);
            } else {
                *(float2*)((float*)Y + (size_t)row * ldc + col)       = make_float2(v00, v01);
                *(float2*)((float*)Y + (size_t)(row + 8) * ldc + col) = make_float2(v10, v11);
            }
        }
    }
}

// ============================================================
// Flash attention (causal), m16n8k16 fp16 HMMA, base-2 softmax.
// AQ=128 queries/CTA (8 warps x 16 rows), AK=64 keys/tile.
// QKV fused buffer (MT, 3072): Q [0,1024), K [1024,2048), V [2048,3072);
// head h at +h*64. Y: fp16 (MT, CC). scale folded: cl = log2(e)/32.
// exp via ex2.approx.f16x2 (P already fp16 for the PV MMA).
// Row sums via P @ ones MMA (no shfl reduction).
// ============================================================
#define AQ 128
#define AK 64
#define ONES16 0x3C003C00u

__global__ __launch_bounds__(256) void attn_mma(
    const __half* __restrict__ QKV, __half* __restrict__ Y)
{
    // Q [0,16K) | K0 [16K,24K) K1 [24K,32K) | V0 [32K,40K) V1 [40K,48K)
    __shared__ __align__(1024) char sm[49152];
    const uint32_t sb = smem_u32(sm);

    const int tid = threadIdx.x, wid = tid >> 5, lid = tid & 31;
    const int bh = blockIdx.y;
    const int b  = bh / HH;
    const int h  = bh % HH;
    const int qt = gridDim.x - 1 - blockIdx.x;   // long blocks first
    const int t0 = qt * AQ;
    const int nkv = 2 * qt + 2;                  // key tiles of 64

    const size_t headoff = (size_t)b * TT * QS + (size_t)h * HD;
    const __half* Qg = QKV + headoff + (size_t)t0 * QS;

    #pragma unroll
    for (int i = 0; i < 4; i++) {
        int idx = tid + i * 256;          // 0..1023
        int r = idx >> 3, ch = idx & 7;
        uint32_t soff = (uint32_t)(r * 128 + ((ch ^ (r & 7)) << 4));
        CP16(sb + soff, Qg + (size_t)r * QS + ch * 8);
    }
    CP_COMMIT();

    auto ld_kv = [&](int buf, int kb) {
        const __half* Kg = QKV + CC   + headoff + (size_t)(kb * AK) * QS;
        const __half* Vg = QKV + 2*CC + headoff + (size_t)(kb * AK) * QS;
        uint32_t kb32 = sb + 16384 + buf * 8192;
        uint32_t vb32 = sb + 32768 + buf * 8192;
        #pragma unroll
        for (int i = 0; i < 2; i++) {
            int idx = tid + i * 256;      // 0..511
            int r = idx >> 3, ch = idx & 7;
            uint32_t soff = (uint32_t)(r * 128 + ((ch ^ (r & 7)) << 4));
            CP16(kb32 + soff, Kg + (size_t)r * QS + ch * 8);
            CP16(vb32 + soff, Vg + (size_t)r * QS + ch * 8);
        }
        CP_COMMIT();
    };

    ld_kv(0, 0);
    ld_kv(1, 1);

    uint32_t qf[4][4];
    float acc[8][4];
    #pragma unroll
    for (int n = 0; n < 8; n++)
        #pragma unroll
        for (int c = 0; c < 4; c++) acc[n][c] = 0.f;
    float m0 = -1e30f, m1 = -1e30f, l0 = 0.f, l1 = 0.f;
    const float cl = 0.04508422f;         // log2(e) / 32  (scale folded)

    const int g = lid >> 2;
    const int tg = lid & 3;
    const int qg0 = t0 + wid * 16 + g;    // global query row (row0)

    for (int kb = 0; kb < nkv; kb++) {
        if (kb + 1 < nkv) { CP_WAIT1(); } else { CP_WAIT0(); }
        __syncthreads();

        if (kb == 0) {
            #pragma unroll
            for (int kk = 0; kk < 4; kk++) {
                int row = wid * 16 + (lid & 7) + ((lid >> 3) & 1) * 8;
                int ch  = 2 * kk + (lid >> 4);
                uint32_t addr = sb + (uint32_t)(row * 128 + ((ch ^ (row & 7)) << 4));
                LDSM4(qf[kk][0], qf[kk][1], qf[kk][2], qf[kk][3], addr);
            }
        }

        const uint32_t kbase = sb + 16384 + (kb & 1) * 8192;
        const uint32_t vbase = sb + 32768 + (kb & 1) * 8192;

        // ---- S = Q K^T (raw, unscaled) ----
        float s[8][4];
        #pragma unroll
        for (int j = 0; j < 8; j++)
            #pragma unroll
            for (int c = 0; c < 4; c++) s[j][c] = 0.f;

        #pragma unroll
        for (int kk = 0; kk < 4; kk++) {
            #pragma unroll
            for (int jp = 0; jp < 4; jp++) {
                int t = lid >> 3;
                int j = 2 * jp + (t >> 1);
                int ch = 2 * kk + (t & 1);
                int keyrow = 8 * j + (lid & 7);
                uint32_t addr = kbase + (uint32_t)(keyrow * 128 + ((ch ^ (keyrow & 7)) << 4));
                uint32_t f0, f1, f2, f3;
                LDSM4(f0, f1, f2, f3, addr);
                MMA16816(s[2 * jp],     qf[kk], f0, f1);
                MMA16816(s[2 * jp + 1], qf[kk], f2, f3);
            }
        }

        if (kb >= nkv - 2) {     // only last two key tiles can hit the diagonal
            #pragma unroll
            for (int j = 0; j < 8; j++) {
                int kc = kb * AK + 8 * j + tg * 2;
                if (kc     > qg0)     s[j][0] = -1e30f;
                if (kc + 1 > qg0)     s[j][1] = -1e30f;
                if (kc     > qg0 + 8) s[j][2] = -1e30f;
                if (kc + 1 > qg0 + 8) s[j][3] = -1e30f;
            }
        }

        // ---- row max (raw domain; cl > 0 so monotone) ----
        float tm0 = -1e30f, tm1 = -1e30f;
        #pragma unroll
        for (int j = 0; j < 8; j++) {
            tm0 = fmaxf(tm0, fmaxf(s[j][0], s[j][1]));
            tm1 = fmaxf(tm1, fmaxf(s[j][2], s[j][3]));
        }
        tm0 = fmaxf(tm0, __shfl_xor_sync(0xffffffffu, tm0, 1));
        tm0 = fmaxf(tm0, __shfl_xor_sync(0xffffffffu, tm0, 2));
        tm1 = fmaxf(tm1, __shfl_xor_sync(0xffffffffu, tm1, 1));
        tm1 = fmaxf(tm1, __shfl_xor_sync(0xffffffffu, tm1, 2));

        float mn0 = fmaxf(m0, tm0 * cl), mn1 = fmaxf(m1, tm1 * cl);
        float cr0 = exp2f(m0 - mn0), cr1 = exp2f(m1 - mn1);
        m0 = mn0; m1 = mn1;

        // ---- P = 2^(s*cl - m) directly into packed fp16 fragments ----
        uint32_t ap[4][4];
        #pragma unroll
        for (int kk = 0; kk < 4; kk++) {
            ap[kk][0] = exp2_pair(fmaf(s[2*kk][0],   cl, -mn0), fmaf(s[2*kk][1],   cl, -mn0));
            ap[kk][1] = exp2_pair(fmaf(s[2*kk][2],   cl, -mn1), fmaf(s[2*kk][3],   cl, -mn1));
            ap[kk][2] = exp2_pair(fmaf(s[2*kk+1][0], cl, -mn0), fmaf(s[2*kk+1][1], cl, -mn0));
            ap[kk][3] = exp2_pair(fmaf(s[2*kk+1][2], cl, -mn1), fmaf(s[2*kk+1][3], cl, -mn1));
        }

        // ---- row sums via P @ ones (fp32 accum, no shfl) ----
        float ld[4] = {0.f, 0.f, 0.f, 0.f};
        #pragma unroll
        for (int kk = 0; kk < 4; kk++)
            MMA16816(ld, ap[kk], ONES16, ONES16);
        l0 = l0 * cr0 + ld[0];
        l1 = l1 * cr1 + ld[2];

        #pragma unroll
        for (int n = 0; n < 8; n++) {
            acc[n][0] *= cr0; acc[n][1] *= cr0;
            acc[n][2] *= cr1; acc[n][3] *= cr1;
        }

        // ---- acc += P V ----
        #pragma unroll
        for (int kk = 0; kk < 4; kk++) {
            #pragma unroll
            for (int np = 0; np < 4; np++) {
                int t = lid >> 3;
                int n = 2 * np + (t >> 1);
                int keyrow = 16 * kk + (t & 1) * 8 + (lid & 7);
                uint32_t addr = vbase + (uint32_t)(keyrow * 128 + ((n ^ (keyrow & 7)) << 4));
                uint32_t f0, f1, f2, f3;
                LDSM4T(f0, f1, f2, f3, addr);
                MMA16816(acc[2 * np],     ap[kk], f0, f1);
                MMA16816(acc[2 * np + 1], ap[kk], f2, f3);
            }
        }

        __syncthreads();
        if (kb + 2 < nkv) ld_kv(kb & 1, kb + 2);
    }

    float inv0 = 1.f / l0, inv1 = 1.f / l1;
    const size_t yoff = (size_t)b * TT * CC + (size_t)h * HD;
    __half* Y0 = Y + yoff + (size_t)(t0 + wid * 16 + g) * CC + tg * 2;
    __half* Y1 = Y0 + 8 * CC;
    #pragma unroll
    for (int n = 0; n < 8; n++) {
        *(__half2*)(Y0 + n * 8) = __floats2half2_rn(acc[n][0] * inv0, acc[n][1] * inv0);
        *(__half2*)(Y1 + n * 8) = __floats2half2_rn(acc[n][2] * inv1, acc[n][3] * inv1);
    }
}

// ============================================================
extern "C" void kernel_launch(void* const* d_in, const int* in_sizes, int n_in,
                              void* d_out, int out_size) {
    const float* x  = (const float*)d_in[0];
    const float* Wq = (const float*)d_in[1];
    const float* bq = (const float*)d_in[2];
    const float* Wk = (const float*)d_in[3];
    const float* bk = (const float*)d_in[4];
    const float* Wv = (const float*)d_in[5];
    const float* bv = (const float*)d_in[6];
    const float* Wo = (const float*)d_in[7];
    const float* bo = (const float*)d_in[8];

    __half *x16, *w16, *qkv16, *y16;
    float *bqkv;
    cudaGetSymbolAddress((void**)&x16,   g_x16);
    cudaGetSymbolAddress((void**)&w16,   g_w16);
    cudaGetSymbolAddress((void**)&qkv16, g_qkv16);
    cudaGetSymbolAddress((void**)&y16,   g_y16);
    cudaGetSymbolAddress((void**)&bqkv,  g_bqkv);

    cudaFuncSetAttribute(gemm_mma<__half>, cudaFuncAttributeMaxDynamicSharedMemorySize, GSMEM);
    cudaFuncSetAttribute(gemm_mma<float>,  cudaFuncAttributeMaxDynamicSharedMemorySize, GSMEM);

    cvt_all<<<3072, 256>>>((const float4*)x, (const float4*)Wq, (const float4*)Wk,
                           (const float4*)Wv, (const float4*)Wo,
                           (__half2*)x16, (__half2*)w16);
    pack_bias<<<QS / 256, 256>>>(bq, bk, bv, bqkv);

    dim3 gqkv(QS / GBN, MT / GBM);   // (24, 64)
    gemm_mma<__half><<<gqkv, 128, GSMEM>>>(x16, w16, bqkv, qkv16, QS);

    dim3 ag(TT / AQ, BB * HH);       // (16, 64)
    attn_mma<<<ag, 256>>>(qkv16, y16);

    dim3 go(CC / GBN, MT / GBM);     // (8, 64)
    gemm_mma<float><<<go, 128, GSMEM>>>(y16, w16 + 3*CC*CC, bo, (float*)d_out, CC);
}

// round 9
// speedup vs baseline: 9.5520x; 1.0264x over previous
#include <cuda_runtime.h>
#include <cuda_fp16.h>
#include <math.h>
#include <stdint.h>

#define BB 4
#define TT 2048
#define CC 1024
#define HH 16
#define HD 64
#define MT (BB*TT)   // 8192
#define QS (3*CC)    // fused QKV row stride = 3072

// ---- scratch (static device arrays; no allocation allowed) ----
__device__ __half g_x16[MT*CC];
__device__ __half g_w16[4*CC*CC];     // Wq,Wk,Wv packed + Wo
__device__ float  g_bqkv[QS];
__device__ __half g_qkv16[(size_t)MT*QS];
__device__ __half g_y16[MT*CC];

// ============================================================
// PTX helpers
// ============================================================
__device__ __forceinline__ uint32_t smem_u32(const void* p) {
    uint32_t a;
    asm("{ .reg .u64 t; cvta.to.shared.u64 t, %1; cvt.u32.u64 %0, t; }" : "=r"(a) : "l"(p));
    return a;
}
#define CP16(dst, src) \
    asm volatile("cp.async.cg.shared.global [%0], [%1], 16;" :: "r"(dst), "l"(src))
#define CP_COMMIT() asm volatile("cp.async.commit_group;" ::: "memory")
#define CP_WAIT2()  asm volatile("cp.async.wait_group 2;" ::: "memory")
#define LDSM4(r0, r1, r2, r3, addr) \
    asm volatile("ldmatrix.sync.aligned.m8n8.x4.shared.b16 {%0,%1,%2,%3}, [%4];" \
                 : "=r"(r0), "=r"(r1), "=r"(r2), "=r"(r3) : "r"(addr))
#define LDSM4T(r0, r1, r2, r3, addr) \
    asm volatile("ldmatrix.sync.aligned.m8n8.x4.trans.shared.b16 {%0,%1,%2,%3}, [%4];" \
                 : "=r"(r0), "=r"(r1), "=r"(r2), "=r"(r3) : "r"(addr))
#define MMA16816(d, a, b0, b1) \
    asm volatile("mma.sync.aligned.m16n8k16.row.col.f32.f16.f16.f32 " \
                 "{%0,%1,%2,%3}, {%4,%5,%6,%7}, {%8,%9}, {%0,%1,%2,%3};" \
                 : "+f"((d)[0]), "+f"((d)[1]), "+f"((d)[2]), "+f"((d)[3]) \
                 : "r"((a)[0]), "r"((a)[1]), "r"((a)[2]), "r"((a)[3]), \
                   "r"(b0), "r"(b1))

// exp2 of two fp32 args -> packed fp16x2 (lo, hi)
__device__ __forceinline__ uint32_t exp2_pair(float lo, float hi) {
    uint32_t h, d;
    asm("cvt.rn.f16x2.f32 %0, %1, %2;" : "=r"(h) : "f"(hi), "f"(lo));
    asm("ex2.approx.f16x2 %0, %1;" : "=r"(d) : "r"(h));
    return d;
}

// ============================================================
// Fused fp32 -> fp16 convert: x (MT*CC) + 4 weights (CC*CC each)
// ============================================================
#define N4X (MT*CC/4)       // 2097152
#define N4W (CC*CC/4)       // 262144
#define N4TOT (N4X + 4*N4W) // 3145728

__global__ __launch_bounds__(256) void cvt_all(
    const float4* __restrict__ x,
    const float4* __restrict__ w0, const float4* __restrict__ w1,
    const float4* __restrict__ w2, const float4* __restrict__ w3,
    __half2* __restrict__ xd, __half2* __restrict__ wd)
{
    const int stride = gridDim.x * blockDim.x;
    for (int i = blockIdx.x * blockDim.x + threadIdx.x; i < N4TOT; i += stride) {
        const float4* s; __half2* d; int off;
        if (i < N4X) { s = x; d = xd; off = i; }
        else {
            int j = i - N4X;
            int rg = j >> 18;                 // N4W = 2^18
            off = j & (N4W - 1);
            s = (rg == 0) ? w0 : (rg == 1) ? w1 : (rg == 2) ? w2 : w3;
            d = wd + (size_t)rg * (2 * N4W);
        }
        float4 v = s[off];
        d[2*off]   = __floats2half2_rn(v.x, v.y);
        d[2*off+1] = __floats2half2_rn(v.z, v.w);
    }
}

__global__ void pack_bias(const float* __restrict__ bq, const float* __restrict__ bk,
                          const float* __restrict__ bv, float* __restrict__ o)
{
    int i = blockIdx.x * blockDim.x + threadIdx.x;   // 0..3071
    const float* src = (i < CC) ? bq : (i < 2*CC) ? bk : bv;
    o[i] = src[i & (CC - 1)];
}

// ============================================================
// HMMA GEMM: Y[m,n] = sum_k A[m,k]*B[n,k] + bias[n]
// BM=128 BN=128 BK=32, 4 warps (2x2), warp tile 64x64, m16n8k16.
// 4-stage cp.async ring, ONE barrier per iteration (prefetch kb+3 into
// the slot freed at kb-1), constant wait_group 2. 2 CTAs/SM.
// ============================================================
#define GBM 128
#define GBN 128
#define GBK 32
#define NKIT (CC/GBK)        // 32
#define A_B 8192             // 128x32 fp16
#define B_B 8192
#define STG_B (A_B + B_B)    // 16384
#define NSTG 4
#define GSMEM (NSTG*STG_B)   // 65536

__device__ __forceinline__ void ld_stage(
    uint32_t sbase, int stage,
    const __half* __restrict__ A, const __half* __restrict__ B,
    int m0, int n0, int k0, int tid)
{
    uint32_t st = sbase + stage * STG_B;
    #pragma unroll
    for (int t = 0; t < 4; t++) {        // 512 chunks each for A and B
        int i = tid + t * 128;
        int r = i >> 2, c = i & 3;
        uint32_t soff = ((uint32_t)(r * 4 + (c ^ (r & 3)))) << 4;
        CP16(st + soff,       A + (size_t)(m0 + r) * CC + k0 + c * 8);
        CP16(st + A_B + soff, B + (size_t)(n0 + r) * CC + k0 + c * 8);
    }
}

template <typename OutT>
__global__ __launch_bounds__(128, 2) void gemm_mma(
    const __half* __restrict__ A, const __half* __restrict__ B,
    const float* __restrict__ bias, OutT* __restrict__ Y, int ldc)
{
    extern __shared__ char smem[];
    const uint32_t sbase = smem_u32(smem);
    const int tid = threadIdx.x, wid = tid >> 5, lid = tid & 31;
    const int m0 = blockIdx.y * GBM, n0 = blockIdx.x * GBN;
    const int wm = wid >> 1, wn = wid & 1;     // 2x2 warp grid, tile 64x64

    float acc[4][8][4];
    #pragma unroll
    for (int a = 0; a < 4; a++)
        #pragma unroll
        for (int b = 0; b < 8; b++)
            #pragma unroll
            for (int c = 0; c < 4; c++) acc[a][b][c] = 0.f;

    // prologue: stages 0,1,2 -> groups G0,G1,G2
    ld_stage(sbase, 0, A, B, m0, n0, 0, tid);       CP_COMMIT();
    ld_stage(sbase, 1, A, B, m0, n0, GBK, tid);     CP_COMMIT();
    ld_stage(sbase, 2, A, B, m0, n0, 2 * GBK, tid); CP_COMMIT();

    const int a_r = wm * 64 + (lid & 15);
    const int a_c = lid >> 4;
    const int b_r = wn * 64 + (lid & 7) + ((lid >> 4) << 3);
    const int b_c = (lid & 15) >> 3;

    for (int kb = 0; kb < NKIT; kb++) {
        // G_kb = stage kb data; exactly 2 newer groups committed -> wait 2
        CP_WAIT2();
        __syncthreads();   // also frees slot (kb-1)%4 (consumed last iter)
        const uint32_t st = sbase + (kb & 3) * STG_B;

        #pragma unroll
        for (int kk = 0; kk < 2; kk++) {
            uint32_t af[4][4], bf[4][4];
            #pragma unroll
            for (int mi = 0; mi < 4; mi++) {
                int r = a_r + mi * 16;
                int c16 = kk * 2 + a_c;
                uint32_t off = ((uint32_t)(r * 4 + (c16 ^ (r & 3)))) << 4;
                LDSM4(af[mi][0], af[mi][1], af[mi][2], af[mi][3], st + off);
            }
            #pragma unroll
            for (int nj = 0; nj < 4; nj++) {
                int r = b_r + nj * 16;
                int c16 = kk * 2 + b_c;
                uint32_t off = ((uint32_t)(r * 4 + (c16 ^ (r & 3)))) << 4;
                LDSM4(bf[nj][0], bf[nj][1], bf[nj][2], bf[nj][3], st + A_B + off);
            }
            #pragma unroll
            for (int mi = 0; mi < 4; mi++)
                #pragma unroll
                for (int nj = 0; nj < 4; nj++) {
                    MMA16816(acc[mi][nj * 2],     af[mi], bf[nj][0], bf[nj][1]);
                    MMA16816(acc[mi][nj * 2 + 1], af[mi], bf[nj][2], bf[nj][3]);
                }
        }
        // prefetch kb+3 into slot (kb+3)%4 == (kb-1)%4 (freed by this iter's sync)
        if (kb + 3 < NKIT)
            ld_stage(sbase, (kb + 3) & 3, A, B, m0, n0, (kb + 3) * GBK, tid);
        CP_COMMIT();   // always commit (possibly empty) to keep group count uniform
    }

    #pragma unroll
    for (int mi = 0; mi < 4; mi++) {
        #pragma unroll
        for (int nj = 0; nj < 8; nj++) {
            int row = m0 + wm * 64 + mi * 16 + (lid >> 2);
            int col = n0 + wn * 64 + nj * 8 + (lid & 3) * 2;
            float b0 = __ldg(bias + col), b1 = __ldg(bias + col + 1);
            float v00 = acc[mi][nj][0] + b0, v01 = acc[mi][nj][1] + b1;
            float v10 = acc[mi][nj][2] + b0, v11 = acc[mi][nj][3] + b1;
            if (sizeof(OutT) == 2) {
                *(__half2*)((__half*)Y + (size_t)row * ldc + col)       = __floats2half2_rn(v00, v01);
                *(__half2*)((__half*)Y + (size_t)(row + 8) * ldc + col) = __floats2half2_rn(v10, v11);
            } else {
                *(float2*)((float*)Y + (size_t)row * ldc + col)       = make_float2(v00, v01);
                *(float2*)((float*)Y + (size_t)(row + 8) * ldc + col) = make_float2(v10, v11);
            }
        }
    }
}

// ============================================================
// Flash attention (causal), m16n8k16 fp16 HMMA, base-2 softmax.
// AQ=128 queries/CTA (8 warps x 16 rows), AK=64 keys/tile.
// 4-slot K and V cp.async rings, ONE barrier per tile, wait_group 2.
// smem: Q [0,16K) | K slots [16K,48K) | V slots [48K,80K)  (dynamic 80KB)
// ============================================================
#define AQ 128
#define AK 64
#define ONES16 0x3C003C00u
#define ASM_K 16384
#define ASM_V 49152
#define ASMEM 81920

__global__ __launch_bounds__(256, 2) void attn_mma(
    const __half* __restrict__ QKV, __half* __restrict__ Y)
{
    extern __shared__ char sm[];
    const uint32_t sb = smem_u32(sm);

    const int tid = threadIdx.x, wid = tid >> 5, lid = tid & 31;
    const int bh = blockIdx.y;
    const int b  = bh / HH;
    const int h  = bh % HH;
    const int qt = gridDim.x - 1 - blockIdx.x;   // long blocks first
    const int t0 = qt * AQ;
    const int nkv = 2 * qt + 2;                  // key tiles of 64

    const size_t headoff = (size_t)b * TT * QS + (size_t)h * HD;
    const __half* Qg = QKV + headoff + (size_t)t0 * QS;

    // ---- G0: Q tile (128x64) ----
    #pragma unroll
    for (int i = 0; i < 4; i++) {
        int idx = tid + i * 256;          // 0..1023
        int r = idx >> 3, ch = idx & 7;
        uint32_t soff = (uint32_t)(r * 128 + ((ch ^ (r & 7)) << 4));
        CP16(sb + soff, Qg + (size_t)r * QS + ch * 8);
    }
    CP_COMMIT();

    auto ld_kv = [&](int slot, int kb) {
        const __half* Kg = QKV + CC   + headoff + (size_t)(kb * AK) * QS;
        const __half* Vg = QKV + 2*CC + headoff + (size_t)(kb * AK) * QS;
        uint32_t kb32 = sb + ASM_K + slot * 8192;
        uint32_t vb32 = sb + ASM_V + slot * 8192;
        #pragma unroll
        for (int i = 0; i < 2; i++) {
            int idx = tid + i * 256;      // 0..511
            int r = idx >> 3, ch = idx & 7;
            uint32_t soff = (uint32_t)(r * 128 + ((ch ^ (r & 7)) << 4));
            CP16(kb32 + soff, Kg + (size_t)r * QS + ch * 8);
            CP16(vb32 + soff, Vg + (size_t)r * QS + ch * 8);
        }
    };

    // prologue: G1=kv0, G2=kv1, G3=kv2 (guarded; commit regardless)
    ld_kv(0, 0);                 CP_COMMIT();
    ld_kv(1, 1);                 CP_COMMIT();   // nkv >= 2 always
    if (nkv > 2) ld_kv(2, 2);    CP_COMMIT();

    uint32_t qf[4][4];
    float acc[8][4];
    #pragma unroll
    for (int n = 0; n < 8; n++)
        #pragma unroll
        for (int c = 0; c < 4; c++) acc[n][c] = 0.f;
    float m0 = -1e30f, m1 = -1e30f, l0 = 0.f, l1 = 0.f;
    const float cl = 0.04508422f;         // log2(e) / 32  (scale folded)

    const int g = lid >> 2;
    const int tg = lid & 3;
    const int qg0 = t0 + wid * 16 + g;    // global query row (row0)

    for (int kb = 0; kb < nkv; kb++) {
        // need G_{kb+1}; exactly 2 newer groups committed -> wait 2
        CP_WAIT2();
        __syncthreads();   // frees KV slot (kb-1)%4 (consumed last iter)

        if (kb == 0) {
            #pragma unroll
            for (int kk = 0; kk < 4; kk++) {
                int row = wid * 16 + (lid & 7) + ((lid >> 3) & 1) * 8;
                int ch  = 2 * kk + (lid >> 4);
                uint32_t addr = sb + (uint32_t)(row * 128 + ((ch ^ (row & 7)) << 4));
                LDSM4(qf[kk][0], qf[kk][1], qf[kk][2], qf[kk][3], addr);
            }
        }

        const uint32_t kbase = sb + ASM_K + (kb & 3) * 8192;
        const uint32_t vbase = sb + ASM_V + (kb & 3) * 8192;

        // ---- S = Q K^T (raw, unscaled) ----
        float s[8][4];
        #pragma unroll
        for (int j = 0; j < 8; j++)
            #pragma unroll
            for (int c = 0; c < 4; c++) s[j][c] = 0.f;

        #pragma unroll
        for (int kk = 0; kk < 4; kk++) {
            #pragma unroll
            for (int jp = 0; jp < 4; jp++) {
                int t = lid >> 3;
                int j = 2 * jp + (t >> 1);
                int ch = 2 * kk + (t & 1);
                int keyrow = 8 * j + (lid & 7);
                uint32_t addr = kbase + (uint32_t)(keyrow * 128 + ((ch ^ (keyrow & 7)) << 4));
                uint32_t f0, f1, f2, f3;
                LDSM4(f0, f1, f2, f3, addr);
                MMA16816(s[2 * jp],     qf[kk], f0, f1);
                MMA16816(s[2 * jp + 1], qf[kk], f2, f3);
            }
        }

        if (kb >= nkv - 2) {     // only last two key tiles can hit the diagonal
            #pragma unroll
            for (int j = 0; j < 8; j++) {
                int kc = kb * AK + 8 * j + tg * 2;
                if (kc     > qg0)     s[j][0] = -1e30f;
                if (kc + 1 > qg0)     s[j][1] = -1e30f;
                if (kc     > qg0 + 8) s[j][2] = -1e30f;
                if (kc + 1 > qg0 + 8) s[j][3] = -1e30f;
            }
        }

        // ---- row max ----
        float tm0 = -1e30f, tm1 = -1e30f;
        #pragma unroll
        for (int j = 0; j < 8; j++) {
            tm0 = fmaxf(tm0, fmaxf(s[j][0], s[j][1]));
            tm1 = fmaxf(tm1, fmaxf(s[j][2], s[j][3]));
        }
        tm0 = fmaxf(tm0, __shfl_xor_sync(0xffffffffu, tm0, 1));
        tm0 = fmaxf(tm0, __shfl_xor_sync(0xffffffffu, tm0, 2));
        tm1 = fmaxf(tm1, __shfl_xor_sync(0xffffffffu, tm1, 1));
        tm1 = fmaxf(tm1, __shfl_xor_sync(0xffffffffu, tm1, 2));

        float mn0 = fmaxf(m0, tm0 * cl), mn1 = fmaxf(m1, tm1 * cl);
        float cr0 = exp2f(m0 - mn0), cr1 = exp2f(m1 - mn1);
        m0 = mn0; m1 = mn1;

        // ---- P = 2^(s*cl - m) into packed fp16 fragments ----
        uint32_t ap[4][4];
        #pragma unroll
        for (int kk = 0; kk < 4; kk++) {
            ap[kk][0] = exp2_pair(fmaf(s[2*kk][0],   cl, -mn0), fmaf(s[2*kk][1],   cl, -mn0));
            ap[kk][1] = exp2_pair(fmaf(s[2*kk][2],   cl, -mn1), fmaf(s[2*kk][3],   cl, -mn1));
            ap[kk][2] = exp2_pair(fmaf(s[2*kk+1][0], cl, -mn0), fmaf(s[2*kk+1][1], cl, -mn0));
            ap[kk][3] = exp2_pair(fmaf(s[2*kk+1][2], cl, -mn1), fmaf(s[2*kk+1][3], cl, -mn1));
        }

        // ---- row sums via P @ ones ----
        float ld[4] = {0.f, 0.f, 0.f, 0.f};
        #pragma unroll
        for (int kk = 0; kk < 4; kk++)
            MMA16816(ld, ap[kk], ONES16, ONES16);
        l0 = l0 * cr0 + ld[0];
        l1 = l1 * cr1 + ld[2];

        #pragma unroll
        for (int n = 0; n < 8; n++) {
            acc[n][0] *= cr0; acc[n][1] *= cr0;
            acc[n][2] *= cr1; acc[n][3] *= cr1;
        }

        // ---- acc += P V ----
        #pragma unroll
        for (int kk = 0; kk < 4; kk++) {
            #pragma unroll
            for (int np = 0; np < 4; np++) {
                int t = lid >> 3;
                int n = 2 * np + (t >> 1);
                int keyrow = 16 * kk + (t & 1) * 8 + (lid & 7);
                uint32_t addr = vbase + (uint32_t)(keyrow * 128 + ((n ^ (keyrow & 7)) << 4));
                uint32_t f0, f1, f2, f3;
                LDSM4T(f0, f1, f2, f3, addr);
                MMA16816(acc[2 * np],     ap[kk], f0, f1);
                MMA16816(acc[2 * np + 1], ap[kk], f2, f3);
            }
        }

        // prefetch kb+3 into slot (kb+3)%4 == (kb-1)%4
        if (kb + 3 < nkv) ld_kv((kb + 3) & 3, kb + 3);
        CP_COMMIT();   // always commit to keep group count uniform
    }

    float inv0 = 1.f / l0, inv1 = 1.f / l1;
    const size_t yoff = (size_t)b * TT * CC + (size_t)h * HD;
    __half* Y0 = Y + yoff + (size_t)(t0 + wid * 16 + g) * CC + tg * 2;
    __half* Y1 = Y0 + 8 * CC;
    #pragma unroll
    for (int n = 0; n < 8; n++) {
        *(__half2*)(Y0 + n * 8) = __floats2half2_rn(acc[n][0] * inv0, acc[n][1] * inv0);
        *(__half2*)(Y1 + n * 8) = __floats2half2_rn(acc[n][2] * inv1, acc[n][3] * inv1);
    }
}

// ============================================================
extern "C" void kernel_launch(void* const* d_in, const int* in_sizes, int n_in,
                              void* d_out, int out_size) {
    const float* x  = (const float*)d_in[0];
    const float* Wq = (const float*)d_in[1];
    const float* bq = (const float*)d_in[2];
    const float* Wk = (const float*)d_in[3];
    const float* bk = (const float*)d_in[4];
    const float* Wv = (const float*)d_in[5];
    const float* bv = (const float*)d_in[6];
    const float* Wo = (const float*)d_in[7];
    const float* bo = (const float*)d_in[8];

    __half *x16, *w16, *qkv16, *y16;
    float *bqkv;
    cudaGetSymbolAddress((void**)&x16,   g_x16);
    cudaGetSymbolAddress((void**)&w16,   g_w16);
    cudaGetSymbolAddress((void**)&qkv16, g_qkv16);
    cudaGetSymbolAddress((void**)&y16,   g_y16);
    cudaGetSymbolAddress((void**)&bqkv,  g_bqkv);

    cudaFuncSetAttribute(gemm_mma<__half>, cudaFuncAttributeMaxDynamicSharedMemorySize, GSMEM);
    cudaFuncSetAttribute(gemm_mma<float>,  cudaFuncAttributeMaxDynamicSharedMemorySize, GSMEM);
    cudaFuncSetAttribute(attn_mma,         cudaFuncAttributeMaxDynamicSharedMemorySize, ASMEM);

    cvt_all<<<3072, 256>>>((const float4*)x, (const float4*)Wq, (const float4*)Wk,
                           (const float4*)Wv, (const float4*)Wo,
                           (__half2*)x16, (__half2*)w16);
    pack_bias<<<QS / 256, 256>>>(bq, bk, bv, bqkv);

    dim3 gqkv(QS / GBN, MT / GBM);   // (24, 64)
    gemm_mma<__half><<<gqkv, 128, GSMEM>>>(x16, w16, bqkv, qkv16, QS);

    dim3 ag(TT / AQ, BB * HH);       // (16, 64)
    attn_mma<<<ag, 256, ASMEM>>>(qkv16, y16);

    dim3 go(CC / GBN, MT / GBM);     // (8, 64)
    gemm_mma<float><<<go, 128, GSMEM>>>(y16, w16 + 3*CC*CC, bo, (float*)d_out, CC);
}